// round 3
// baseline (speedup 1.0000x reference)
#include <cuda_runtime.h>
#include <math.h>
#include <stdint.h>

// Problem dims
#define BB    256     // batch
#define NA    128     // atoms / timesteps
#define INF   128     // in features
#define HH    256     // hidden
#define G3    768     // 3*H
#define VV    6       // MAX_VAL
#define OUTF  256
#define KFC   1536    // VV*HH

// ---------------- scratch (static device memory; no allocations) -------------
__device__ float g_xproj[(size_t)BB * NA * G3];   // [b, t, 768]  (b_ih folded)
__device__ float g_rnn  [(size_t)BB * NA * HH];   // [b, t, 256]  GRU outputs

// ---------------- generic fp32 NT GEMM tile params ---------------------------
#define BM 128
#define BN 64
#define BK 16
#define TM 8
#define TN 4

// ---------------- x_proj GEMM: M=32768, N=768, K=128 -------------------------
__global__ __launch_bounds__(256, 2)
void k_gemm_xproj(const float* __restrict__ A, const float* __restrict__ W,
                  const float* __restrict__ bias)
{
    __shared__ float As[BK][BM + 4];
    __shared__ float Ws[BK][BN + 4];
    const int K = INF;

    int tid = threadIdx.x;
    int tx = tid & 15, ty = tid >> 4;
    int m0 = blockIdx.y * BM;
    int n0 = blockIdx.x * BN;

    float acc[TM][TN];
#pragma unroll
    for (int i = 0; i < TM; i++)
#pragma unroll
        for (int j = 0; j < TN; j++) acc[i][j] = 0.f;

    for (int k0 = 0; k0 < K; k0 += BK) {
#pragma unroll
        for (int l = 0; l < 2; l++) {
            int i = tid + l * 256;
            int m = i >> 2, kq = i & 3;
            float4 v = *(const float4*)(A + (size_t)(m0 + m) * K + k0 + kq * 4);
            As[kq * 4 + 0][m] = v.x; As[kq * 4 + 1][m] = v.y;
            As[kq * 4 + 2][m] = v.z; As[kq * 4 + 3][m] = v.w;
        }
        {
            int n = tid >> 2, kq = tid & 3;
            float4 v = *(const float4*)(W + (size_t)(n0 + n) * K + k0 + kq * 4);
            Ws[kq * 4 + 0][n] = v.x; Ws[kq * 4 + 1][n] = v.y;
            Ws[kq * 4 + 2][n] = v.z; Ws[kq * 4 + 3][n] = v.w;
        }
        __syncthreads();
#pragma unroll
        for (int k = 0; k < BK; k++) {
            float a[TM], w[TN];
#pragma unroll
            for (int i = 0; i < TM; i++) a[i] = As[k][ty * TM + i];
#pragma unroll
            for (int j = 0; j < TN; j++) w[j] = Ws[k][tx * TN + j];
#pragma unroll
            for (int i = 0; i < TM; i++)
#pragma unroll
                for (int j = 0; j < TN; j++)
                    acc[i][j] = fmaf(a[i], w[j], acc[i][j]);
        }
        __syncthreads();
    }
#pragma unroll
    for (int i = 0; i < TM; i++) {
        int m = m0 + ty * TM + i;
        float4 o;
        int n = n0 + tx * TN;
        o.x = acc[i][0] + bias[n + 0];
        o.y = acc[i][1] + bias[n + 1];
        o.z = acc[i][2] + bias[n + 2];
        o.w = acc[i][3] + bias[n + 3];
        *(float4*)(g_xproj + (size_t)m * G3 + n) = o;
    }
}

// ---------------- FC GEMM with gathered A: M=32768, N=256, K=1536 -----------
__global__ __launch_bounds__(256, 2)
void k_gemm_fc(const int* __restrict__ bonded, const float* __restrict__ Wfc,
               const float* __restrict__ bfc, float* __restrict__ Out)
{
    __shared__ float As[BK][BM + 4];
    __shared__ float Ws[BK][BN + 4];
    __shared__ int   idx_s[BM][VV];
    const int K = KFC, N = OUTF;

    int tid = threadIdx.x;
    int tx = tid & 15, ty = tid >> 4;
    int b  = blockIdx.y;
    int n0 = blockIdx.x * BN;

    for (int i = tid; i < BM * VV; i += 256)
        idx_s[i / VV][i % VV] = bonded[(size_t)b * NA * VV + i];
    __syncthreads();

    float acc[TM][TN];
#pragma unroll
    for (int i = 0; i < TM; i++)
#pragma unroll
        for (int j = 0; j < TN; j++) acc[i][j] = 0.f;

    for (int k0 = 0; k0 < K; k0 += BK) {
        int v   = k0 >> 8;
        int hh0 = k0 & 255;
#pragma unroll
        for (int l = 0; l < 2; l++) {
            int i = tid + l * 256;
            int m = i >> 2, kq = i & 3;
            int a = idx_s[m][v];
            float4 val = *(const float4*)(g_rnn + ((size_t)b * NA + a) * HH + hh0 + kq * 4);
            As[kq * 4 + 0][m] = val.x; As[kq * 4 + 1][m] = val.y;
            As[kq * 4 + 2][m] = val.z; As[kq * 4 + 3][m] = val.w;
        }
        {
            int n = tid >> 2, kq = tid & 3;
            float4 val = *(const float4*)(Wfc + (size_t)(n0 + n) * K + k0 + kq * 4);
            Ws[kq * 4 + 0][n] = val.x; Ws[kq * 4 + 1][n] = val.y;
            Ws[kq * 4 + 2][n] = val.z; Ws[kq * 4 + 3][n] = val.w;
        }
        __syncthreads();
#pragma unroll
        for (int k = 0; k < BK; k++) {
            float a[TM], w[TN];
#pragma unroll
            for (int i = 0; i < TM; i++) a[i] = As[k][ty * TM + i];
#pragma unroll
            for (int j = 0; j < TN; j++) w[j] = Ws[k][tx * TN + j];
#pragma unroll
            for (int i = 0; i < TM; i++)
#pragma unroll
                for (int j = 0; j < TN; j++)
                    acc[i][j] = fmaf(a[i], w[j], acc[i][j]);
        }
        __syncthreads();
    }
#pragma unroll
    for (int i = 0; i < TM; i++) {
        int m = b * NA + ty * TM + i;
        int n = n0 + tx * TN;
        float4 o;
        float y0 = acc[i][0] + bfc[n + 0];
        float y1 = acc[i][1] + bfc[n + 1];
        float y2 = acc[i][2] + bfc[n + 2];
        float y3 = acc[i][3] + bfc[n + 3];
        o.x = y0 >= 0.f ? y0 : 0.1f * y0;
        o.y = y1 >= 0.f ? y1 : 0.1f * y1;
        o.z = y2 >= 0.f ? y2 : 0.1f * y2;
        o.w = y3 >= 0.f ? y3 : 0.1f * y3;
        *(float4*)(Out + (size_t)m * N + n) = o;
    }
}

// ---------------- persistent cluster GRU -------------------------------------
// 16 clusters x 8 CTAs, 256 threads/CTA. Cluster owns 16 batches; CTA rank r
// owns hidden slice [32r, 32r+32). W_hh slice (96KB) SMEM-resident all 128
// steps. h double-buffered [2][16][260] (pad 260 -> conflict-free LDS.128).
// Per-step sync: DSMEM push + split cluster barrier (arrive ... wait).

__device__ __forceinline__ void st_cluster_f32(uint32_t laddr, uint32_t rank, float v)
{
    uint32_t raddr;
    asm volatile("mapa.shared::cluster.u32 %0, %1, %2;" : "=r"(raddr) : "r"(laddr), "r"(rank));
    asm volatile("st.shared::cluster.f32 [%0], %1;" :: "r"(raddr), "f"(v) : "memory");
}

__device__ __forceinline__ uint32_t smem_u32(const void* p)
{
    uint32_t a;
    asm("{ .reg .u64 t; cvta.to.shared.u64 t, %1; cvt.u32.u64 %0, t; }" : "=r"(a) : "l"(p));
    return a;
}

#define HPAD     260
#define H_STRIDE (16 * HPAD)                 // floats per h buffer
#define W_F4     (64 * 96)                   // float4 count of W slice
#define GRU_SMEM ((W_F4 * 4 + 2 * H_STRIDE) * 4)   // 131584 bytes

__global__ void __cluster_dims__(8, 1, 1) __launch_bounds__(256, 1)
k_gru_persist(const float* __restrict__ W_hh, const float* __restrict__ b_hh)
{
    extern __shared__ float sm[];
    float4* Wf4 = (float4*)sm;               // [k4 0..63][row 0..95], row = g*32+j
    float*  hs  = sm + W_F4 * 4;             // [2][16][HPAD]

    const int tid  = threadIdx.x;
    const int w    = tid >> 5;
    const int lane = tid & 31;
    const int jl   = lane & 3;               // j within warp's quad
    const int bg   = lane >> 2;              // 0..7
    uint32_t rank;
    asm("mov.u32 %0, %%cluster_ctarank;" : "=r"(rank));
    const int b0    = (blockIdx.x >> 3) * 16;
    const int jloc  = w * 4 + jl;            // 0..31
    const int jglob = (int)rank * 32 + jloc; // 0..255
    const int bA = bg, bB = bg + 8;          // the two batches this thread owns

    // ---- load W slice once (coalesced 16B) ----
    for (int i = tid; i < W_F4; i += 256) {
        int row = i >> 6, k4 = i & 63;
        int g = row >> 5, j = row & 31;
        Wf4[k4 * 96 + row] =
            *(const float4*)(W_hh + ((size_t)(g * 256 + (int)rank * 32 + j)) * 256 + k4 * 4);
    }
    // zero h buffer 0 (t=0 state)
    for (int i = tid; i < H_STRIDE; i += 256) hs[i] = 0.f;
    __syncthreads();

    const float br = b_hh[jglob], bz = b_hh[256 + jglob], bn = b_hh[512 + jglob];
    const uint32_t hs_addr = smem_u32(hs);

    for (int t = 0; t < NA; t++) {
        const float* hc = hs + (t & 1) * H_STRIDE;
        const uint32_t hn_base = hs_addr + (uint32_t)(((t + 1) & 1) * H_STRIDE) * 4u;

        // prefetch xproj (DRAM latency covered by GEMM below)
        const float* xpA = g_xproj + ((size_t)(b0 + bA) * NA + t) * G3 + jglob;
        const float* xpB = g_xproj + ((size_t)(b0 + bB) * NA + t) * G3 + jglob;
        float xrA = __ldg(xpA), xzA = __ldg(xpA + 256), xnA = __ldg(xpA + 512);
        float xrB = __ldg(xpB), xzB = __ldg(xpB + 256), xnB = __ldg(xpB + 512);

        float a00 = 0.f, a01 = 0.f, a02 = 0.f;
        float a10 = 0.f, a11 = 0.f, a12 = 0.f;

#pragma unroll 8
        for (int k4 = 0; k4 < 64; k4++) {
            float4 w0 = Wf4[k4 * 96 + jloc];
            float4 w1 = Wf4[k4 * 96 + 32 + jloc];
            float4 w2 = Wf4[k4 * 96 + 64 + jloc];
            float4 hA = *(const float4*)(hc + bA * HPAD + k4 * 4);
            float4 hB = *(const float4*)(hc + bB * HPAD + k4 * 4);
            a00 = fmaf(hA.x, w0.x, a00); a00 = fmaf(hA.y, w0.y, a00);
            a00 = fmaf(hA.z, w0.z, a00); a00 = fmaf(hA.w, w0.w, a00);
            a01 = fmaf(hA.x, w1.x, a01); a01 = fmaf(hA.y, w1.y, a01);
            a01 = fmaf(hA.z, w1.z, a01); a01 = fmaf(hA.w, w1.w, a01);
            a02 = fmaf(hA.x, w2.x, a02); a02 = fmaf(hA.y, w2.y, a02);
            a02 = fmaf(hA.z, w2.z, a02); a02 = fmaf(hA.w, w2.w, a02);
            a10 = fmaf(hB.x, w0.x, a10); a10 = fmaf(hB.y, w0.y, a10);
            a10 = fmaf(hB.z, w0.z, a10); a10 = fmaf(hB.w, w0.w, a10);
            a11 = fmaf(hB.x, w1.x, a11); a11 = fmaf(hB.y, w1.y, a11);
            a11 = fmaf(hB.z, w1.z, a11); a11 = fmaf(hB.w, w1.w, a11);
            a12 = fmaf(hB.x, w2.x, a12); a12 = fmaf(hB.y, w2.y, a12);
            a12 = fmaf(hB.z, w2.z, a12); a12 = fmaf(hB.w, w2.w, a12);
        }

        // gates + h_new
        float rA = 1.f / (1.f + __expf(-(xrA + a00 + br)));
        float zA = 1.f / (1.f + __expf(-(xzA + a01 + bz)));
        float nA = tanhf(xnA + rA * (a02 + bn));
        float hpA = hc[bA * HPAD + jglob];
        float hnewA = (1.f - zA) * nA + zA * hpA;

        float rB = 1.f / (1.f + __expf(-(xrB + a10 + br)));
        float zB = 1.f / (1.f + __expf(-(xzB + a11 + bz)));
        float nB = tanhf(xnB + rB * (a12 + bn));
        float hpB = hc[bB * HPAD + jglob];
        float hnewB = (1.f - zB) * nB + zB * hpB;

        // push to all 8 cluster CTAs (incl. self)
        uint32_t laddrA = hn_base + (uint32_t)(bA * HPAD + jglob) * 4u;
        uint32_t laddrB = hn_base + (uint32_t)(bB * HPAD + jglob) * 4u;
#pragma unroll
        for (uint32_t c = 0; c < 8; c++) {
            st_cluster_f32(laddrA, c, hnewA);
            st_cluster_f32(laddrB, c, hnewB);
        }

        // publish (release), hide g_rnn stores in barrier shadow, then wait
        asm volatile("barrier.cluster.arrive.aligned;" ::: "memory");
        g_rnn[((size_t)(b0 + bA) * NA + t) * HH + jglob] = hnewA;
        g_rnn[((size_t)(b0 + bB) * NA + t) * HH + jglob] = hnewB;
        asm volatile("barrier.cluster.wait.aligned;" ::: "memory");
    }
}

// ---------------- launch ------------------------------------------------------
extern "C" void kernel_launch(void* const* d_in, const int* in_sizes, int n_in,
                              void* d_out, int out_size)
{
    const float* x      = (const float*)d_in[0];
    const int*   bonded = (const int*)  d_in[1];
    const float* W_ih   = (const float*)d_in[2];
    const float* W_hh   = (const float*)d_in[3];
    const float* b_ih   = (const float*)d_in[4];
    const float* b_hh   = (const float*)d_in[5];
    const float* W_fc   = (const float*)d_in[6];
    const float* b_fc   = (const float*)d_in[7];
    float* out = (float*)d_out;

    cudaFuncSetAttribute(k_gru_persist,
                         cudaFuncAttributeMaxDynamicSharedMemorySize, GRU_SMEM);

    // 1) x_proj = x @ W_ih^T + b_ih   (M=32768, N=768, K=128)
    k_gemm_xproj<<<dim3(G3 / BN, (BB * NA) / BM), 256>>>(x, W_ih, b_ih);

    // 2) GRU: persistent, 16 clusters x 8 CTAs, W resident in SMEM
    k_gru_persist<<<128, 256, GRU_SMEM>>>(W_hh, b_hh);

    // 3) gather + FC + leaky relu  (M=32768, N=256, K=1536)
    k_gemm_fc<<<dim3(OUTF / BN, BB), 256>>>(bonded, W_fc, b_fc, out);
}

// round 4
// speedup vs baseline: 1.1281x; 1.1281x over previous
#include <cuda_runtime.h>
#include <math.h>
#include <stdint.h>

// Problem dims
#define BB    256     // batch
#define NA    128     // atoms / timesteps
#define INF   128     // in features
#define HH    256     // hidden
#define G3    768     // 3*H
#define VV    6       // MAX_VAL
#define OUTF  256
#define KFC   1536    // VV*HH

// ---------------- scratch (static device memory; no allocations) -------------
__device__ float g_xproj[(size_t)BB * NA * G3];   // [b, t, 768]  (b_ih folded)
__device__ float g_rnn  [(size_t)BB * NA * HH];   // [b, t, 256]  GRU outputs

// ---------------- dummy (shifts ncu capture slot) ----------------------------
__global__ void k_dummy() {}

// ---------------- generic fp32 NT GEMM tile params ---------------------------
#define BM 128
#define BN 64
#define BK 16
#define TM 8
#define TN 4

// ---------------- x_proj GEMM: M=32768, N=768, K=128 -------------------------
__global__ __launch_bounds__(256, 2)
void k_gemm_xproj(const float* __restrict__ A, const float* __restrict__ W,
                  const float* __restrict__ bias)
{
    __shared__ float As[BK][BM + 4];
    __shared__ float Ws[BK][BN + 4];
    const int K = INF;

    int tid = threadIdx.x;
    int tx = tid & 15, ty = tid >> 4;
    int m0 = blockIdx.y * BM;
    int n0 = blockIdx.x * BN;

    float acc[TM][TN];
#pragma unroll
    for (int i = 0; i < TM; i++)
#pragma unroll
        for (int j = 0; j < TN; j++) acc[i][j] = 0.f;

    for (int k0 = 0; k0 < K; k0 += BK) {
#pragma unroll
        for (int l = 0; l < 2; l++) {
            int i = tid + l * 256;
            int m = i >> 2, kq = i & 3;
            float4 v = *(const float4*)(A + (size_t)(m0 + m) * K + k0 + kq * 4);
            As[kq * 4 + 0][m] = v.x; As[kq * 4 + 1][m] = v.y;
            As[kq * 4 + 2][m] = v.z; As[kq * 4 + 3][m] = v.w;
        }
        {
            int n = tid >> 2, kq = tid & 3;
            float4 v = *(const float4*)(W + (size_t)(n0 + n) * K + k0 + kq * 4);
            Ws[kq * 4 + 0][n] = v.x; Ws[kq * 4 + 1][n] = v.y;
            Ws[kq * 4 + 2][n] = v.z; Ws[kq * 4 + 3][n] = v.w;
        }
        __syncthreads();
#pragma unroll
        for (int k = 0; k < BK; k++) {
            float a[TM], w[TN];
#pragma unroll
            for (int i = 0; i < TM; i++) a[i] = As[k][ty * TM + i];
#pragma unroll
            for (int j = 0; j < TN; j++) w[j] = Ws[k][tx * TN + j];
#pragma unroll
            for (int i = 0; i < TM; i++)
#pragma unroll
                for (int j = 0; j < TN; j++)
                    acc[i][j] = fmaf(a[i], w[j], acc[i][j]);
        }
        __syncthreads();
    }
#pragma unroll
    for (int i = 0; i < TM; i++) {
        int m = m0 + ty * TM + i;
        float4 o;
        int n = n0 + tx * TN;
        o.x = acc[i][0] + bias[n + 0];
        o.y = acc[i][1] + bias[n + 1];
        o.z = acc[i][2] + bias[n + 2];
        o.w = acc[i][3] + bias[n + 3];
        *(float4*)(g_xproj + (size_t)m * G3 + n) = o;
    }
}

// ---------------- FC GEMM with gathered A: M=32768, N=256, K=1536 -----------
__global__ __launch_bounds__(256, 2)
void k_gemm_fc(const int* __restrict__ bonded, const float* __restrict__ Wfc,
               const float* __restrict__ bfc, float* __restrict__ Out)
{
    __shared__ float As[BK][BM + 4];
    __shared__ float Ws[BK][BN + 4];
    __shared__ int   idx_s[BM][VV];
    const int K = KFC, N = OUTF;

    int tid = threadIdx.x;
    int tx = tid & 15, ty = tid >> 4;
    int b  = blockIdx.y;
    int n0 = blockIdx.x * BN;

    for (int i = tid; i < BM * VV; i += 256)
        idx_s[i / VV][i % VV] = bonded[(size_t)b * NA * VV + i];
    __syncthreads();

    float acc[TM][TN];
#pragma unroll
    for (int i = 0; i < TM; i++)
#pragma unroll
        for (int j = 0; j < TN; j++) acc[i][j] = 0.f;

    for (int k0 = 0; k0 < K; k0 += BK) {
        int v   = k0 >> 8;
        int hh0 = k0 & 255;
#pragma unroll
        for (int l = 0; l < 2; l++) {
            int i = tid + l * 256;
            int m = i >> 2, kq = i & 3;
            int a = idx_s[m][v];
            float4 val = *(const float4*)(g_rnn + ((size_t)b * NA + a) * HH + hh0 + kq * 4);
            As[kq * 4 + 0][m] = val.x; As[kq * 4 + 1][m] = val.y;
            As[kq * 4 + 2][m] = val.z; As[kq * 4 + 3][m] = val.w;
        }
        {
            int n = tid >> 2, kq = tid & 3;
            float4 val = *(const float4*)(Wfc + (size_t)(n0 + n) * K + k0 + kq * 4);
            Ws[kq * 4 + 0][n] = val.x; Ws[kq * 4 + 1][n] = val.y;
            Ws[kq * 4 + 2][n] = val.z; Ws[kq * 4 + 3][n] = val.w;
        }
        __syncthreads();
#pragma unroll
        for (int k = 0; k < BK; k++) {
            float a[TM], w[TN];
#pragma unroll
            for (int i = 0; i < TM; i++) a[i] = As[k][ty * TM + i];
#pragma unroll
            for (int j = 0; j < TN; j++) w[j] = Ws[k][tx * TN + j];
#pragma unroll
            for (int i = 0; i < TM; i++)
#pragma unroll
                for (int j = 0; j < TN; j++)
                    acc[i][j] = fmaf(a[i], w[j], acc[i][j]);
        }
        __syncthreads();
    }
#pragma unroll
    for (int i = 0; i < TM; i++) {
        int m = b * NA + ty * TM + i;
        int n = n0 + tx * TN;
        float4 o;
        float y0 = acc[i][0] + bfc[n + 0];
        float y1 = acc[i][1] + bfc[n + 1];
        float y2 = acc[i][2] + bfc[n + 2];
        float y3 = acc[i][3] + bfc[n + 3];
        o.x = y0 >= 0.f ? y0 : 0.1f * y0;
        o.y = y1 >= 0.f ? y1 : 0.1f * y1;
        o.z = y2 >= 0.f ? y2 : 0.1f * y2;
        o.w = y3 >= 0.f ? y3 : 0.1f * y3;
        *(float4*)(Out + (size_t)m * N + n) = o;
    }
}

// ---------------- persistent cluster GRU (k-split) ---------------------------
// 16 clusters x 8 CTAs x 256 threads. Cluster owns 16 batches; CTA rank r owns
// hidden slice [32r,32r+32). W slice SMEM-resident (skewed layout) all steps.
// Thread = (j: warp*4+jl, 4 batches: bidx+4s, khalf): accumulates over its
// 128-k half; shfl.xor(16) merges halves. Both halves compute gates; each half
// pushes h_new to 4 of the 8 cluster CTAs (DSMEM), khalf=0 also stores g_rnn.

__device__ __forceinline__ void st_cluster_f32(uint32_t laddr, uint32_t rank, float v)
{
    uint32_t raddr;
    asm volatile("mapa.shared::cluster.u32 %0, %1, %2;" : "=r"(raddr) : "r"(laddr), "r"(rank));
    asm volatile("st.shared::cluster.f32 [%0], %1;" :: "r"(raddr), "f"(v) : "memory");
}

__device__ __forceinline__ uint32_t smem_u32(const void* p)
{
    uint32_t a;
    asm("{ .reg .u64 t; cvta.to.shared.u64 t, %1; cvt.u32.u64 %0, t; }" : "=r"(a) : "l"(p));
    return a;
}

// W float4 index: k-half skew (+4 float4 = 64B) makes the two khalf wavefront
// halves land in complementary bank halves. Row stride 100 float4.
#define W4IDX(k4, r)  ((k4) * 100 + (((k4) >> 5) << 2) + (r))
#define W4_COUNT      6400
// h word offset within a buffer: row stride 276 words; upper 128 j's offset by
// +16 words (64B) -> khalf halves complementary, b*276 spreads granules.
#define HROW          276
#define HBUF          (16 * HROW)            // 4416 words per buffer
#define HOFF(b, j)    ((b) * HROW + (j) + (((j) >> 7) << 4))
#define HK4(b, k4)    ((b) * HROW + (k4) * 4 + (((k4) >> 5) << 4))

#define GRU_SMEM ((W4_COUNT * 4 + 2 * HBUF) * 4)   // 137728 bytes

__global__ void __cluster_dims__(8, 1, 1) __launch_bounds__(256, 1)
k_gru_persist(const float* __restrict__ W_hh, const float* __restrict__ b_hh)
{
    extern __shared__ float sm[];
    float4* Wf4 = (float4*)sm;               // skewed W slice
    float*  hs  = sm + W4_COUNT * 4;         // 2 x HBUF

    const int tid   = threadIdx.x;
    const int w_    = tid >> 5;              // warp 0..7 -> j quad
    const int lane  = tid & 31;
    const int jl    = lane & 3;
    const int bidx  = (lane >> 2) & 3;
    const int khalf = lane >> 4;             // 0/1 -> k in [0,128) / [128,256)
    uint32_t rank;
    asm("mov.u32 %0, %%cluster_ctarank;" : "=r"(rank));
    const int b0    = (blockIdx.x >> 3) * 16;
    const int jloc  = w_ * 4 + jl;           // 0..31
    const int jglob = (int)rank * 32 + jloc; // 0..255
    const int kk0   = khalf * 32;            // this thread's k4 base

    // ---- load W slice once (coalesced GMEM, skewed SMEM) ----
    for (int i = tid; i < 96 * 64; i += 256) {
        int k4 = i & 63, r = i >> 6;         // r = g*32 + j
        int g = r >> 5, j = r & 31;
        Wf4[W4IDX(k4, r)] =
            *(const float4*)(W_hh + ((size_t)(g * 256 + (int)rank * 32 + j)) * 256 + k4 * 4);
    }
    // zero h buffer 0 (t=0 state), pads included
    for (int i = tid; i < HBUF; i += 256) hs[i] = 0.f;
    __syncthreads();

    const float br = b_hh[jglob], bz = b_hh[256 + jglob], bn = b_hh[512 + jglob];
    const uint32_t hs_addr = smem_u32(hs);
    const uint32_t rbase = (uint32_t)khalf * 4u;   // this half pushes ranks rbase..rbase+3

    for (int t = 0; t < NA; t++) {
        const float* hc = hs + (t & 1) * HBUF;
        const uint32_t hn_base = hs_addr + (uint32_t)(((t + 1) & 1) * HBUF) * 4u;

        // prefetch xproj for my 4 batches x 3 gates (hidden behind GEMM)
        float xr[4], xz[4], xn[4];
#pragma unroll
        for (int s = 0; s < 4; s++) {
            const float* xp = g_xproj + ((size_t)(b0 + bidx + 4 * s) * NA + t) * G3 + jglob;
            xr[s] = __ldg(xp);
            xz[s] = __ldg(xp + 256);
            xn[s] = __ldg(xp + 512);
        }

        float a0[4], a1[4], a2[4];
#pragma unroll
        for (int s = 0; s < 4; s++) { a0[s] = 0.f; a1[s] = 0.f; a2[s] = 0.f; }

#pragma unroll 4
        for (int kk = 0; kk < 32; kk++) {
            int k4 = kk0 + kk;
            float4 w0 = Wf4[W4IDX(k4, jloc)];
            float4 w1 = Wf4[W4IDX(k4, 32 + jloc)];
            float4 w2 = Wf4[W4IDX(k4, 64 + jloc)];
#pragma unroll
            for (int s = 0; s < 4; s++) {
                float4 hv = *(const float4*)(hc + HK4(bidx + 4 * s, k4));
                a0[s] = fmaf(hv.x, w0.x, a0[s]); a0[s] = fmaf(hv.y, w0.y, a0[s]);
                a0[s] = fmaf(hv.z, w0.z, a0[s]); a0[s] = fmaf(hv.w, w0.w, a0[s]);
                a1[s] = fmaf(hv.x, w1.x, a1[s]); a1[s] = fmaf(hv.y, w1.y, a1[s]);
                a1[s] = fmaf(hv.z, w1.z, a1[s]); a1[s] = fmaf(hv.w, w1.w, a1[s]);
                a2[s] = fmaf(hv.x, w2.x, a2[s]); a2[s] = fmaf(hv.y, w2.y, a2[s]);
                a2[s] = fmaf(hv.z, w2.z, a2[s]); a2[s] = fmaf(hv.w, w2.w, a2[s]);
            }
        }

        // merge the two k-halves (partner = lane ^ 16); both sides get totals
#pragma unroll
        for (int s = 0; s < 4; s++) {
            a0[s] += __shfl_xor_sync(0xffffffffu, a0[s], 16);
            a1[s] += __shfl_xor_sync(0xffffffffu, a1[s], 16);
            a2[s] += __shfl_xor_sync(0xffffffffu, a2[s], 16);
        }

        // gates + h_new (both halves compute; stores split by half)
#pragma unroll
        for (int s = 0; s < 4; s++) {
            int b = bidx + 4 * s;
            float r = 1.f / (1.f + __expf(-(xr[s] + a0[s] + br)));
            float z = 1.f / (1.f + __expf(-(xz[s] + a1[s] + bz)));
            float n = tanhf(xn[s] + r * (a2[s] + bn));
            float hp = hc[HOFF(b, jglob)];
            float hnew = (1.f - z) * n + z * hp;

            uint32_t laddr = hn_base + (uint32_t)HOFF(b, jglob) * 4u;
#pragma unroll
            for (uint32_t c = 0; c < 4; c++)
                st_cluster_f32(laddr, rbase + c, hnew);

            if (khalf == 0)
                g_rnn[((size_t)(b0 + b) * NA + t) * HH + jglob] = hnew;
        }

        asm volatile("barrier.cluster.arrive.aligned;" ::: "memory");
        asm volatile("barrier.cluster.wait.aligned;" ::: "memory");
    }
}

// ---------------- launch ------------------------------------------------------
extern "C" void kernel_launch(void* const* d_in, const int* in_sizes, int n_in,
                              void* d_out, int out_size)
{
    const float* x      = (const float*)d_in[0];
    const int*   bonded = (const int*)  d_in[1];
    const float* W_ih   = (const float*)d_in[2];
    const float* W_hh   = (const float*)d_in[3];
    const float* b_ih   = (const float*)d_in[4];
    const float* b_hh   = (const float*)d_in[5];
    const float* W_fc   = (const float*)d_in[6];
    const float* b_fc   = (const float*)d_in[7];
    float* out = (float*)d_out;

    cudaFuncSetAttribute(k_gru_persist,
                         cudaFuncAttributeMaxDynamicSharedMemorySize, GRU_SMEM);

    // 0) dummy: shifts the ncu capture slot (diagnostic)
    k_dummy<<<1, 32>>>();

    // 1) x_proj = x @ W_ih^T + b_ih   (M=32768, N=768, K=128)
    k_gemm_xproj<<<dim3(G3 / BN, (BB * NA) / BM), 256>>>(x, W_ih, b_ih);

    // 2) GRU: persistent, 16 clusters x 8 CTAs, k-split threads
    k_gru_persist<<<128, 256, GRU_SMEM>>>(W_hh, b_hh);

    // 3) gather + FC + leaky relu  (M=32768, N=256, K=1536)
    k_gemm_fc<<<dim3(OUTF / BN, BB), 256>>>(bonded, W_fc, b_fc, out);
}

// round 6
// speedup vs baseline: 1.4846x; 1.3160x over previous
#include <cuda_runtime.h>
#include <math.h>
#include <stdint.h>

// Problem dims
#define BB    256
#define NA    128
#define INF   128
#define HH    256
#define G3    768
#define VV    6
#define OUTF  256
#define KFC   1536

// ---------------- scratch ----------------------------------------------------
__device__ float g_xproj[(size_t)BB * NA * G3];
__device__ float g_rnn  [(size_t)BB * NA * HH];

__global__ void k_dummy() {}

// ---------------- helpers ----------------------------------------------------
__device__ __forceinline__ uint32_t smem_u32(const void* p)
{
    uint32_t a;
    asm("{ .reg .u64 t; cvta.to.shared.u64 t, %1; cvt.u32.u64 %0, t; }" : "=r"(a) : "l"(p));
    return a;
}

__device__ __forceinline__ uint32_t f2tf32(float v)
{
    uint32_t u;
    asm("cvt.rna.tf32.f32 %0, %1;" : "=r"(u) : "f"(v));
    return u;
}

__device__ __forceinline__ void mma_tf32_16n8k8(float* c, uint32_t a0, uint32_t a1,
                                                uint32_t a2, uint32_t a3,
                                                uint32_t b0, uint32_t b1)
{
    asm volatile(
        "mma.sync.aligned.m16n8k8.row.col.f32.tf32.tf32.f32 "
        "{%0,%1,%2,%3}, {%4,%5,%6,%7}, {%8,%9}, {%0,%1,%2,%3};"
        : "+f"(c[0]), "+f"(c[1]), "+f"(c[2]), "+f"(c[3])
        : "r"(a0), "r"(a1), "r"(a2), "r"(a3), "r"(b0), "r"(b1));
}

// ============================================================================
// tf32 warp-mma GEMM: C[128,128] = A[128,K] * W[128,K]^T per CTA tile.
// 8 warps as 2(m) x 4(n); warp tile 64x32; mma m16n8k8.
// SMEM: As[m][k] / Ws[n][k], stride 36 words (conflict-free frag loads).
// ============================================================================

#define GK   32     // K chunk

// ---------------- x_proj: M=(b,t), N=768, K=128 ------------------------------
__global__ __launch_bounds__(256, 2)
void k_xproj_mma(const float* __restrict__ X, const float* __restrict__ Wih,
                 const float* __restrict__ bias)
{
    __shared__ uint32_t As[128][36];
    __shared__ uint32_t Ws[128][36];

    const int tid = threadIdx.x, lane = tid & 31, wid = tid >> 5;
    const int warpM = wid >> 2, warpN = wid & 3;
    const int b = blockIdx.y, n0 = blockIdx.x * 128;
    const int g = lane >> 2, q = lane & 3;

    float acc[4][4][4];
#pragma unroll
    for (int i = 0; i < 4; i++)
#pragma unroll
        for (int j = 0; j < 4; j++)
#pragma unroll
            for (int r = 0; r < 4; r++) acc[i][j][r] = 0.f;

    for (int c = 0; c < INF / GK; c++) {
        const int k0 = c * GK;
#pragma unroll
        for (int l = 0; l < 4; l++) {
            int f = tid + l * 256;
            int row = f >> 3, c4 = f & 7;
            float4 v = *(const float4*)(X + ((size_t)b * NA + row) * INF + k0 + c4 * 4);
            *(uint4*)&As[row][c4 * 4] =
                make_uint4(f2tf32(v.x), f2tf32(v.y), f2tf32(v.z), f2tf32(v.w));
            float4 w = *(const float4*)(Wih + (size_t)(n0 + row) * INF + k0 + c4 * 4);
            *(uint4*)&Ws[row][c4 * 4] =
                make_uint4(f2tf32(w.x), f2tf32(w.y), f2tf32(w.z), f2tf32(w.w));
        }
        __syncthreads();
#pragma unroll
        for (int kk = 0; kk < GK; kk += 8) {
            uint32_t bf[4][2];
#pragma unroll
            for (int nt = 0; nt < 4; nt++) {
                int nb = warpN * 32 + nt * 8 + g;
                bf[nt][0] = Ws[nb][kk + q];
                bf[nt][1] = Ws[nb][kk + q + 4];
            }
#pragma unroll
            for (int mt = 0; mt < 4; mt++) {
                int mb = warpM * 64 + mt * 16 + g;
                uint32_t a0 = As[mb][kk + q];
                uint32_t a1 = As[mb + 8][kk + q];
                uint32_t a2 = As[mb][kk + q + 4];
                uint32_t a3 = As[mb + 8][kk + q + 4];
#pragma unroll
                for (int nt = 0; nt < 4; nt++)
                    mma_tf32_16n8k8(acc[mt][nt], a0, a1, a2, a3, bf[nt][0], bf[nt][1]);
            }
        }
        __syncthreads();
    }

    // epilogue: bias add, store fp32
#pragma unroll
    for (int mt = 0; mt < 4; mt++) {
#pragma unroll
        for (int nt = 0; nt < 4; nt++) {
            int mrow = warpM * 64 + mt * 16 + g;
            int ncol = n0 + warpN * 32 + nt * 8 + 2 * q;
            float b0 = __ldg(bias + ncol), b1 = __ldg(bias + ncol + 1);
            float* o = g_xproj + ((size_t)b * NA + mrow) * G3 + ncol;
            *(float2*)o = make_float2(acc[mt][nt][0] + b0, acc[mt][nt][1] + b1);
            float* o2 = o + 8 * G3;
            *(float2*)o2 = make_float2(acc[mt][nt][2] + b0, acc[mt][nt][3] + b1);
        }
    }
}

// ---------------- FC: gather + M=128, N=256(2 tiles), K=1536 ----------------
__global__ __launch_bounds__(256, 2)
void k_fc_mma(const int* __restrict__ bonded, const float* __restrict__ Wfc,
              const float* __restrict__ bfc, float* __restrict__ Out)
{
    __shared__ uint32_t As[128][36];
    __shared__ uint32_t Ws[128][36];
    __shared__ int idx_s[NA * VV];

    const int tid = threadIdx.x, lane = tid & 31, wid = tid >> 5;
    const int warpM = wid >> 2, warpN = wid & 3;
    const int b = blockIdx.y, n0 = blockIdx.x * 128;
    const int g = lane >> 2, q = lane & 3;

    for (int i = tid; i < NA * VV; i += 256)
        idx_s[i] = bonded[(size_t)b * NA * VV + i];

    float acc[4][4][4];
#pragma unroll
    for (int i = 0; i < 4; i++)
#pragma unroll
        for (int j = 0; j < 4; j++)
#pragma unroll
            for (int r = 0; r < 4; r++) acc[i][j][r] = 0.f;

    const float* rnn_b = g_rnn + (size_t)b * NA * HH;
    __syncthreads();

    for (int c = 0; c < KFC / GK; c++) {
        const int v = c >> 3, hsub = (c << 5) & 255, k0 = c * GK;
#pragma unroll
        for (int l = 0; l < 4; l++) {
            int f = tid + l * 256;
            int row = f >> 3, c4 = f & 7;
            float4 val = *(const float4*)(rnn_b + (size_t)idx_s[row * VV + v] * HH + hsub + c4 * 4);
            *(uint4*)&As[row][c4 * 4] =
                make_uint4(f2tf32(val.x), f2tf32(val.y), f2tf32(val.z), f2tf32(val.w));
            float4 w = *(const float4*)(Wfc + (size_t)(n0 + row) * KFC + k0 + c4 * 4);
            *(uint4*)&Ws[row][c4 * 4] =
                make_uint4(f2tf32(w.x), f2tf32(w.y), f2tf32(w.z), f2tf32(w.w));
        }
        __syncthreads();
#pragma unroll
        for (int kk = 0; kk < GK; kk += 8) {
            uint32_t bf[4][2];
#pragma unroll
            for (int nt = 0; nt < 4; nt++) {
                int nb = warpN * 32 + nt * 8 + g;
                bf[nt][0] = Ws[nb][kk + q];
                bf[nt][1] = Ws[nb][kk + q + 4];
            }
#pragma unroll
            for (int mt = 0; mt < 4; mt++) {
                int mb = warpM * 64 + mt * 16 + g;
                uint32_t a0 = As[mb][kk + q];
                uint32_t a1 = As[mb + 8][kk + q];
                uint32_t a2 = As[mb][kk + q + 4];
                uint32_t a3 = As[mb + 8][kk + q + 4];
#pragma unroll
                for (int nt = 0; nt < 4; nt++)
                    mma_tf32_16n8k8(acc[mt][nt], a0, a1, a2, a3, bf[nt][0], bf[nt][1]);
            }
        }
        __syncthreads();
    }

    // epilogue: bias + leaky relu
#pragma unroll
    for (int mt = 0; mt < 4; mt++) {
#pragma unroll
        for (int nt = 0; nt < 4; nt++) {
            int mrow = warpM * 64 + mt * 16 + g;
            int ncol = n0 + warpN * 32 + nt * 8 + 2 * q;
            float b0 = __ldg(bfc + ncol), b1 = __ldg(bfc + ncol + 1);
            float y0 = acc[mt][nt][0] + b0, y1 = acc[mt][nt][1] + b1;
            float y2 = acc[mt][nt][2] + b0, y3 = acc[mt][nt][3] + b1;
            y0 = y0 >= 0.f ? y0 : 0.1f * y0;
            y1 = y1 >= 0.f ? y1 : 0.1f * y1;
            y2 = y2 >= 0.f ? y2 : 0.1f * y2;
            y3 = y3 >= 0.f ? y3 : 0.1f * y3;
            float* o = Out + ((size_t)b * NA + mrow) * OUTF + ncol;
            *(float2*)o = make_float2(y0, y1);
            *(float2*)(o + 8 * OUTF) = make_float2(y2, y3);
        }
    }
}

// ---------------- persistent cluster GRU (R2 best variant) -------------------
__device__ __forceinline__ void st_cluster_f32(uint32_t laddr, uint32_t rank, float v)
{
    uint32_t raddr;
    asm volatile("mapa.shared::cluster.u32 %0, %1, %2;" : "=r"(raddr) : "r"(laddr), "r"(rank));
    asm volatile("st.shared::cluster.f32 [%0], %1;" :: "r"(raddr), "f"(v) : "memory");
}

#define W_FLOATS (64 * 96 * 4)
#define H_FLOATS (16 * 256)
#define GRU_SMEM ((W_FLOATS + 2 * H_FLOATS) * 4)

__global__ void __cluster_dims__(8, 1, 1) __launch_bounds__(128, 1)
k_gru_persist(const float* __restrict__ W_hh, const float* __restrict__ b_hh)
{
    extern __shared__ float sm[];
    float* Wsm = sm;
    float* hs  = sm + W_FLOATS;

    const int tid  = threadIdx.x;
    const int lane = tid & 31;
    const int bq   = tid >> 5;
    uint32_t rank;
    asm("mov.u32 %0, %%cluster_ctarank;" : "=r"(rank));
    const int b0    = (blockIdx.x >> 3) * 16;
    const int jglob = (int)rank * 32 + lane;

    for (int i = tid; i < 96 * 64; i += 128) {
        int row = i >> 6, k4 = i & 63;
        int g = row >> 5, j = row & 31;
        float4 v = *(const float4*)(W_hh + ((size_t)(g * 256 + (int)rank * 32 + j)) * 256 + k4 * 4);
        float* d = Wsm + (size_t)(k4 * 96 + row) * 4;
        d[0] = v.x; d[1] = v.y; d[2] = v.z; d[3] = v.w;
    }
    for (int i = tid; i < H_FLOATS; i += 128) hs[i] = 0.f;
    __syncthreads();

    const float br = b_hh[jglob], bz = b_hh[256 + jglob], bn = b_hh[512 + jglob];
    const uint32_t hs_addr = smem_u32(hs);

    for (int t = 0; t < NA; t++) {
        const float* hc = hs + (t & 1) * H_FLOATS;
        const uint32_t hn_off = ((t + 1) & 1) * H_FLOATS;

        float xr[4], xz[4], xn[4];
#pragma unroll
        for (int b = 0; b < 4; b++) {
            const float* xp = g_xproj + ((size_t)(b0 + bq * 4 + b) * NA + t) * G3 + jglob;
            xr[b] = __ldg(xp);
            xz[b] = __ldg(xp + 256);
            xn[b] = __ldg(xp + 512);
        }

        float acc[4][3];
#pragma unroll
        for (int b = 0; b < 4; b++)
#pragma unroll
            for (int g = 0; g < 3; g++) acc[b][g] = 0.f;

#pragma unroll 4
        for (int k4 = 0; k4 < 64; k4++) {
            float4 wv[3];
#pragma unroll
            for (int g = 0; g < 3; g++)
                wv[g] = *(const float4*)(Wsm + (size_t)(k4 * 96 + g * 32 + lane) * 4);
#pragma unroll
            for (int b = 0; b < 4; b++) {
                float4 hv = *(const float4*)(hc + (bq * 4 + b) * 256 + k4 * 4);
#pragma unroll
                for (int g = 0; g < 3; g++) {
                    acc[b][g] = fmaf(hv.x, wv[g].x, acc[b][g]);
                    acc[b][g] = fmaf(hv.y, wv[g].y, acc[b][g]);
                    acc[b][g] = fmaf(hv.z, wv[g].z, acc[b][g]);
                    acc[b][g] = fmaf(hv.w, wv[g].w, acc[b][g]);
                }
            }
        }

#pragma unroll
        for (int b = 0; b < 4; b++) {
            float r = 1.f / (1.f + __expf(-(xr[b] + acc[b][0] + br)));
            float z = 1.f / (1.f + __expf(-(xz[b] + acc[b][1] + bz)));
            float n = tanhf(xn[b] + r * (acc[b][2] + bn));
            float hp = hc[(bq * 4 + b) * 256 + jglob];
            float hv2 = (1.f - z) * n + z * hp;

            g_rnn[((size_t)(b0 + bq * 4 + b) * NA + t) * HH + jglob] = hv2;

            uint32_t laddr = hs_addr + (hn_off + (bq * 4 + b) * 256 + jglob) * 4;
#pragma unroll
            for (uint32_t c = 0; c < 8; c++) st_cluster_f32(laddr, c, hv2);
        }

        asm volatile("barrier.cluster.arrive.aligned;" ::: "memory");
        asm volatile("barrier.cluster.wait.aligned;" ::: "memory");
    }
}

// ---------------- launch ------------------------------------------------------
extern "C" void kernel_launch(void* const* d_in, const int* in_sizes, int n_in,
                              void* d_out, int out_size)
{
    const float* x      = (const float*)d_in[0];
    const int*   bonded = (const int*)  d_in[1];
    const float* W_ih   = (const float*)d_in[2];
    const float* W_hh   = (const float*)d_in[3];
    const float* b_ih   = (const float*)d_in[4];
    const float* b_hh   = (const float*)d_in[5];
    const float* W_fc   = (const float*)d_in[6];
    const float* b_fc   = (const float*)d_in[7];
    float* out = (float*)d_out;

    cudaFuncSetAttribute(k_gru_persist,
                         cudaFuncAttributeMaxDynamicSharedMemorySize, GRU_SMEM);

    // two dummies: absolute launch #3 (the profiled one) = k_gru_persist
    k_dummy<<<1, 32>>>();
    k_dummy<<<1, 32>>>();

    // 1) x_proj (tf32 mma)
    k_xproj_mma<<<dim3(G3 / 128, BB), 256>>>(x, W_ih, b_ih);

    // 2) GRU persistent cluster kernel (fp32)
    k_gru_persist<<<128, 128, GRU_SMEM>>>(W_hh, b_hh);

    // 3) FC (tf32 mma, gather fused)
    k_fc_mma<<<dim3(OUTF / 128, BB), 256>>>(bonded, W_fc, b_fc, out);
}

// round 8
// speedup vs baseline: 1.9589x; 1.3194x over previous
#include <cuda_runtime.h>
#include <math.h>
#include <stdint.h>

// Problem dims
#define BB    256
#define NA    128
#define INF   128
#define HH    256
#define G3    768
#define VV    6
#define OUTF  256
#define KFC   1536

// ---------------- scratch ----------------------------------------------------
__device__ float g_xproj[(size_t)BB * NA * G3];
__device__ float g_rnn  [(size_t)BB * NA * HH];

__global__ void k_dummy() {}

// ---------------- helpers ----------------------------------------------------
__device__ __forceinline__ uint32_t smem_u32(const void* p)
{
    uint32_t a;
    asm("{ .reg .u64 t; cvta.to.shared.u64 t, %1; cvt.u32.u64 %0, t; }" : "=r"(a) : "l"(p));
    return a;
}

__device__ __forceinline__ uint32_t f2tf32(float v)
{
    uint32_t u;
    asm("cvt.rna.tf32.f32 %0, %1;" : "=r"(u) : "f"(v));
    return u;
}

__device__ __forceinline__ void mma_tf32_16n8k8(float* c, uint32_t a0, uint32_t a1,
                                                uint32_t a2, uint32_t a3,
                                                uint32_t b0, uint32_t b1)
{
    asm volatile(
        "mma.sync.aligned.m16n8k8.row.col.f32.tf32.tf32.f32 "
        "{%0,%1,%2,%3}, {%4,%5,%6,%7}, {%8,%9}, {%0,%1,%2,%3};"
        : "+f"(c[0]), "+f"(c[1]), "+f"(c[2]), "+f"(c[3])
        : "r"(a0), "r"(a1), "r"(a2), "r"(a3), "r"(b0), "r"(b1));
}

__device__ __forceinline__ void st_cluster_u64(uint32_t laddr, uint32_t rank,
                                               float x, float y)
{
    uint32_t raddr;
    uint64_t pv;
    asm("mov.b64 %0, {%1, %2};" : "=l"(pv) : "f"(x), "f"(y));
    asm volatile("mapa.shared::cluster.u32 %0, %1, %2;" : "=r"(raddr) : "r"(laddr), "r"(rank));
    asm volatile("st.shared::cluster.u64 [%0], %1;" :: "r"(raddr), "l"(pv) : "memory");
}

// ============================================================================
// tf32 warp-mma GEMM (validated R6): C[128,128] tiles, 8 warps 2x4, m16n8k8
// ============================================================================
#define GK 32

__global__ __launch_bounds__(256, 2)
void k_xproj_mma(const float* __restrict__ X, const float* __restrict__ Wih,
                 const float* __restrict__ bias)
{
    __shared__ uint32_t As[128][36];
    __shared__ uint32_t Ws[128][36];

    const int tid = threadIdx.x, lane = tid & 31, wid = tid >> 5;
    const int warpM = wid >> 2, warpN = wid & 3;
    const int b = blockIdx.y, n0 = blockIdx.x * 128;
    const int g = lane >> 2, q = lane & 3;

    float acc[4][4][4];
#pragma unroll
    for (int i = 0; i < 4; i++)
#pragma unroll
        for (int j = 0; j < 4; j++)
#pragma unroll
            for (int r = 0; r < 4; r++) acc[i][j][r] = 0.f;

    for (int c = 0; c < INF / GK; c++) {
        const int k0 = c * GK;
#pragma unroll
        for (int l = 0; l < 4; l++) {
            int f = tid + l * 256;
            int row = f >> 3, c4 = f & 7;
            float4 v = *(const float4*)(X + ((size_t)b * NA + row) * INF + k0 + c4 * 4);
            *(uint4*)&As[row][c4 * 4] =
                make_uint4(f2tf32(v.x), f2tf32(v.y), f2tf32(v.z), f2tf32(v.w));
            float4 w = *(const float4*)(Wih + (size_t)(n0 + row) * INF + k0 + c4 * 4);
            *(uint4*)&Ws[row][c4 * 4] =
                make_uint4(f2tf32(w.x), f2tf32(w.y), f2tf32(w.z), f2tf32(w.w));
        }
        __syncthreads();
#pragma unroll
        for (int kk = 0; kk < GK; kk += 8) {
            uint32_t bf[4][2];
#pragma unroll
            for (int nt = 0; nt < 4; nt++) {
                int nb = warpN * 32 + nt * 8 + g;
                bf[nt][0] = Ws[nb][kk + q];
                bf[nt][1] = Ws[nb][kk + q + 4];
            }
#pragma unroll
            for (int mt = 0; mt < 4; mt++) {
                int mb = warpM * 64 + mt * 16 + g;
                uint32_t a0 = As[mb][kk + q];
                uint32_t a1 = As[mb + 8][kk + q];
                uint32_t a2 = As[mb][kk + q + 4];
                uint32_t a3 = As[mb + 8][kk + q + 4];
#pragma unroll
                for (int nt = 0; nt < 4; nt++)
                    mma_tf32_16n8k8(acc[mt][nt], a0, a1, a2, a3, bf[nt][0], bf[nt][1]);
            }
        }
        __syncthreads();
    }

#pragma unroll
    for (int mt = 0; mt < 4; mt++) {
#pragma unroll
        for (int nt = 0; nt < 4; nt++) {
            int mrow = warpM * 64 + mt * 16 + g;
            int ncol = n0 + warpN * 32 + nt * 8 + 2 * q;
            float b0 = __ldg(bias + ncol), b1 = __ldg(bias + ncol + 1);
            float* o = g_xproj + ((size_t)b * NA + mrow) * G3 + ncol;
            *(float2*)o = make_float2(acc[mt][nt][0] + b0, acc[mt][nt][1] + b1);
            float* o2 = o + 8 * G3;
            *(float2*)o2 = make_float2(acc[mt][nt][2] + b0, acc[mt][nt][3] + b1);
        }
    }
}

__global__ __launch_bounds__(256, 2)
void k_fc_mma(const int* __restrict__ bonded, const float* __restrict__ Wfc,
              const float* __restrict__ bfc, float* __restrict__ Out)
{
    __shared__ uint32_t As[128][36];
    __shared__ uint32_t Ws[128][36];
    __shared__ int idx_s[NA * VV];

    const int tid = threadIdx.x, lane = tid & 31, wid = tid >> 5;
    const int warpM = wid >> 2, warpN = wid & 3;
    const int b = blockIdx.y, n0 = blockIdx.x * 128;
    const int g = lane >> 2, q = lane & 3;

    for (int i = tid; i < NA * VV; i += 256)
        idx_s[i] = bonded[(size_t)b * NA * VV + i];

    float acc[4][4][4];
#pragma unroll
    for (int i = 0; i < 4; i++)
#pragma unroll
        for (int j = 0; j < 4; j++)
#pragma unroll
            for (int r = 0; r < 4; r++) acc[i][j][r] = 0.f;

    const float* rnn_b = g_rnn + (size_t)b * NA * HH;
    __syncthreads();

    for (int c = 0; c < KFC / GK; c++) {
        const int v = c >> 3, hsub = (c << 5) & 255, k0 = c * GK;
#pragma unroll
        for (int l = 0; l < 4; l++) {
            int f = tid + l * 256;
            int row = f >> 3, c4 = f & 7;
            float4 val = *(const float4*)(rnn_b + (size_t)idx_s[row * VV + v] * HH + hsub + c4 * 4);
            *(uint4*)&As[row][c4 * 4] =
                make_uint4(f2tf32(val.x), f2tf32(val.y), f2tf32(val.z), f2tf32(val.w));
            float4 w = *(const float4*)(Wfc + (size_t)(n0 + row) * KFC + k0 + c4 * 4);
            *(uint4*)&Ws[row][c4 * 4] =
                make_uint4(f2tf32(w.x), f2tf32(w.y), f2tf32(w.z), f2tf32(w.w));
        }
        __syncthreads();
#pragma unroll
        for (int kk = 0; kk < GK; kk += 8) {
            uint32_t bf[4][2];
#pragma unroll
            for (int nt = 0; nt < 4; nt++) {
                int nb = warpN * 32 + nt * 8 + g;
                bf[nt][0] = Ws[nb][kk + q];
                bf[nt][1] = Ws[nb][kk + q + 4];
            }
#pragma unroll
            for (int mt = 0; mt < 4; mt++) {
                int mb = warpM * 64 + mt * 16 + g;
                uint32_t a0 = As[mb][kk + q];
                uint32_t a1 = As[mb + 8][kk + q];
                uint32_t a2 = As[mb][kk + q + 4];
                uint32_t a3 = As[mb + 8][kk + q + 4];
#pragma unroll
                for (int nt = 0; nt < 4; nt++)
                    mma_tf32_16n8k8(acc[mt][nt], a0, a1, a2, a3, bf[nt][0], bf[nt][1]);
            }
        }
        __syncthreads();
    }

#pragma unroll
    for (int mt = 0; mt < 4; mt++) {
#pragma unroll
        for (int nt = 0; nt < 4; nt++) {
            int mrow = warpM * 64 + mt * 16 + g;
            int ncol = n0 + warpN * 32 + nt * 8 + 2 * q;
            float b0 = __ldg(bfc + ncol), b1 = __ldg(bfc + ncol + 1);
            float y0 = acc[mt][nt][0] + b0, y1 = acc[mt][nt][1] + b1;
            float y2 = acc[mt][nt][2] + b0, y3 = acc[mt][nt][3] + b1;
            y0 = y0 >= 0.f ? y0 : 0.1f * y0;
            y1 = y1 >= 0.f ? y1 : 0.1f * y1;
            y2 = y2 >= 0.f ? y2 : 0.1f * y2;
            y3 = y3 >= 0.f ? y3 : 0.1f * y3;
            float* o = Out + ((size_t)b * NA + mrow) * OUTF + ncol;
            *(float2*)o = make_float2(y0, y1);
            *(float2*)(o + 8 * OUTF) = make_float2(y2, y3);
        }
    }
}

// ============================================================================
// GRU on tensor cores (FIXED addressing): 16 clusters x 8 CTAs x 128 thr.
// CTA rank owns j-slice [32r,32r+32). Warp w: j in [8w,8w+8); lane (g,q) owns
// batches (g, g+8) x j-pair (8w+2q, 8w+2q+1). h buffers hold GLOBAL j 0..255
// per batch row — h_prev reads and DSMEM pushes use jg0 = rank*32 + jb.
// ============================================================================
#define GWS   260                    // h/W smem word stride
#define GW_WORDS (96 * GWS)          // 24960
#define GH_BUF   (16 * GWS)          // 4160 words per h buffer
#define GRU_SMEM ((GW_WORDS + 2 * GH_BUF) * 4)   // 133120 B

__global__ void __cluster_dims__(8, 1, 1) __launch_bounds__(128, 1)
k_gru_mma(const float* __restrict__ W_hh, const float* __restrict__ b_hh)
{
    extern __shared__ uint32_t smg[];
    uint32_t* Wsm = smg;
    float*    hs  = (float*)(smg + GW_WORDS);

    const int tid = threadIdx.x, lane = tid & 31, w = tid >> 5;
    const int g = lane >> 2, q = lane & 3;
    uint32_t rank;
    asm("mov.u32 %0, %%cluster_ctarank;" : "=r"(rank));
    const int b0  = (blockIdx.x >> 3) * 16;       // cluster batch base
    const int jb  = w * 8 + 2 * q;                // local j pair base (0..30)
    const int jg0 = (int)rank * 32 + jb;          // GLOBAL j pair base
    const int bA  = b0 + g, bBt = b0 + g + 8;     // my two global batches

    // ---- W slice -> tf32 SMEM (row = gate*32 + jloc, stride GWS) ----
    for (int i = tid; i < 96 * 64; i += 128) {
        int r = i >> 6, k4 = i & 63;
        int gate = r >> 5, jl = r & 31;
        float4 v = *(const float4*)(W_hh +
            ((size_t)(gate * 256 + (int)rank * 32 + jl)) * 256 + k4 * 4);
        uint32_t* d = Wsm + (size_t)r * GWS + k4 * 4;
        d[0] = f2tf32(v.x); d[1] = f2tf32(v.y);
        d[2] = f2tf32(v.z); d[3] = f2tf32(v.w);
    }
    for (int i = tid; i < GH_BUF; i += 128) hs[i] = 0.f;
    __syncthreads();

    const float2 brv = *(const float2*)(b_hh + jg0);
    const float2 bzv = *(const float2*)(b_hh + 256 + jg0);
    const float2 bnv = *(const float2*)(b_hh + 512 + jg0);
    const uint32_t hs_addr = smem_u32(hs);
    const uint32_t* WR = Wsm + (size_t)(0  + w * 8 + g) * GWS;
    const uint32_t* WZ = Wsm + (size_t)(32 + w * 8 + g) * GWS;
    const uint32_t* WN = Wsm + (size_t)(64 + w * 8 + g) * GWS;

    for (int t = 0; t < NA; t++) {
        const float* hc = hs + (t & 1) * GH_BUF;
        const uint32_t hn_base = hs_addr + (uint32_t)(((t + 1) & 1) * GH_BUF) * 4u;

        // prefetch xproj (pairs) for my 2 batches x 3 gates
        const float* xpA = g_xproj + ((size_t)bA  * NA + t) * G3 + jg0;
        const float* xpB = g_xproj + ((size_t)bBt * NA + t) * G3 + jg0;
        float2 xrA = __ldg((const float2*)xpA);
        float2 xzA = __ldg((const float2*)(xpA + 256));
        float2 xnA = __ldg((const float2*)(xpA + 512));
        float2 xrB = __ldg((const float2*)xpB);
        float2 xzB = __ldg((const float2*)(xpB + 256));
        float2 xnB = __ldg((const float2*)(xpB + 512));

        float aR[4] = {0.f, 0.f, 0.f, 0.f};
        float aZ[4] = {0.f, 0.f, 0.f, 0.f};
        float aN[4] = {0.f, 0.f, 0.f, 0.f};

        const float* hA = hc + g * GWS;          // batch row g (full 256 j)
        const float* hB = hc + (g + 8) * GWS;    // batch row g+8
#pragma unroll 4
        for (int kk = 0; kk < 256; kk += 8) {
            uint32_t a0 = f2tf32(hA[kk + q]);
            uint32_t a1 = f2tf32(hB[kk + q]);
            uint32_t a2 = f2tf32(hA[kk + q + 4]);
            uint32_t a3 = f2tf32(hB[kk + q + 4]);
            mma_tf32_16n8k8(aR, a0, a1, a2, a3, WR[kk + q], WR[kk + q + 4]);
            mma_tf32_16n8k8(aZ, a0, a1, a2, a3, WZ[kk + q], WZ[kk + q + 4]);
            mma_tf32_16n8k8(aN, a0, a1, a2, a3, WN[kk + q], WN[kk + q + 4]);
        }

        // gates: acc idx 0:(bA,j0) 1:(bA,j1) 2:(bB,j0) 3:(bB,j1)
        float2 hpA = *(const float2*)(hc + g * GWS + jg0);        // FIXED: global j
        float2 hpB = *(const float2*)(hc + (g + 8) * GWS + jg0);  // FIXED: global j

        float r0 = 1.f / (1.f + __expf(-(xrA.x + aR[0] + brv.x)));
        float r1 = 1.f / (1.f + __expf(-(xrA.y + aR[1] + brv.y)));
        float r2 = 1.f / (1.f + __expf(-(xrB.x + aR[2] + brv.x)));
        float r3 = 1.f / (1.f + __expf(-(xrB.y + aR[3] + brv.y)));
        float z0 = 1.f / (1.f + __expf(-(xzA.x + aZ[0] + bzv.x)));
        float z1 = 1.f / (1.f + __expf(-(xzA.y + aZ[1] + bzv.y)));
        float z2 = 1.f / (1.f + __expf(-(xzB.x + aZ[2] + bzv.x)));
        float z3 = 1.f / (1.f + __expf(-(xzB.y + aZ[3] + bzv.y)));
        float n0v = tanhf(xnA.x + r0 * (aN[0] + bnv.x));
        float n1v = tanhf(xnA.y + r1 * (aN[1] + bnv.y));
        float n2v = tanhf(xnB.x + r2 * (aN[2] + bnv.x));
        float n3v = tanhf(xnB.y + r3 * (aN[3] + bnv.y));

        float h0 = (1.f - z0) * n0v + z0 * hpA.x;
        float h1 = (1.f - z1) * n1v + z1 * hpA.y;
        float h2 = (1.f - z2) * n2v + z2 * hpB.x;
        float h3 = (1.f - z3) * n3v + z3 * hpB.y;

        // push j-pairs (8B) at GLOBAL j offset to all 8 cluster CTAs
        uint32_t laddrA = hn_base + (uint32_t)(g * GWS + jg0) * 4u;        // FIXED
        uint32_t laddrB = hn_base + (uint32_t)((g + 8) * GWS + jg0) * 4u;  // FIXED
#pragma unroll
        for (uint32_t c = 0; c < 8; c++) {
            st_cluster_u64(laddrA, c, h0, h1);
            st_cluster_u64(laddrB, c, h2, h3);
        }

        asm volatile("barrier.cluster.arrive.aligned;" ::: "memory");
        *(float2*)(g_rnn + ((size_t)bA  * NA + t) * HH + jg0) = make_float2(h0, h1);
        *(float2*)(g_rnn + ((size_t)bBt * NA + t) * HH + jg0) = make_float2(h2, h3);
        asm volatile("barrier.cluster.wait.aligned;" ::: "memory");
    }
}

// ---------------- launch ------------------------------------------------------
extern "C" void kernel_launch(void* const* d_in, const int* in_sizes, int n_in,
                              void* d_out, int out_size)
{
    const float* x      = (const float*)d_in[0];
    const int*   bonded = (const int*)  d_in[1];
    const float* W_ih   = (const float*)d_in[2];
    const float* W_hh   = (const float*)d_in[3];
    const float* b_ih   = (const float*)d_in[4];
    const float* b_hh   = (const float*)d_in[5];
    const float* W_fc   = (const float*)d_in[6];
    const float* b_fc   = (const float*)d_in[7];
    float* out = (float*)d_out;

    cudaFuncSetAttribute(k_gru_mma,
                         cudaFuncAttributeMaxDynamicSharedMemorySize, GRU_SMEM);

    // two dummies: absolute launch #3 (profiled) = k_gru_mma
    k_dummy<<<1, 32>>>();
    k_dummy<<<1, 32>>>();

    // 1) x_proj (tf32 mma)
    k_xproj_mma<<<dim3(G3 / 128, BB), 256>>>(x, W_ih, b_ih);

    // 2) GRU on tensor cores (tf32 mma, fp32 state)
    k_gru_mma<<<128, 128, GRU_SMEM>>>(W_hh, b_hh);

    // 3) FC (tf32 mma, gather fused)
    k_fc_mma<<<dim3(OUTF / 128, BB), 256>>>(bonded, W_fc, b_fc, out);
}

// round 10
// speedup vs baseline: 2.0177x; 1.0300x over previous
#include <cuda_runtime.h>
#include <math.h>
#include <stdint.h>

// Problem dims
#define BB    256
#define NA    128
#define INF   128
#define HH    256
#define G3    768
#define VV    6
#define OUTF  256
#define KFC   1536

// ---------------- scratch ----------------------------------------------------
__device__ float g_xproj[(size_t)BB * NA * G3];
__device__ float g_rnn  [(size_t)BB * NA * HH];

__global__ void k_dummy() {}

// ---------------- helpers ----------------------------------------------------
__device__ __forceinline__ uint32_t smem_u32(const void* p)
{
    uint32_t a;
    asm("{ .reg .u64 t; cvta.to.shared.u64 t, %1; cvt.u32.u64 %0, t; }" : "=r"(a) : "l"(p));
    return a;
}

__device__ __forceinline__ uint32_t f2tf32(float v)
{
    uint32_t u;
    asm("cvt.rna.tf32.f32 %0, %1;" : "=r"(u) : "f"(v));
    return u;
}

__device__ __forceinline__ void mma_tf32_16n8k8(float* c, uint32_t a0, uint32_t a1,
                                                uint32_t a2, uint32_t a3,
                                                uint32_t b0, uint32_t b1)
{
    asm volatile(
        "mma.sync.aligned.m16n8k8.row.col.f32.tf32.tf32.f32 "
        "{%0,%1,%2,%3}, {%4,%5,%6,%7}, {%8,%9}, {%0,%1,%2,%3};"
        : "+f"(c[0]), "+f"(c[1]), "+f"(c[2]), "+f"(c[3])
        : "r"(a0), "r"(a1), "r"(a2), "r"(a3), "r"(b0), "r"(b1));
}

__device__ __forceinline__ void st_cluster_u32pair(uint32_t laddr, uint32_t rank,
                                                   uint32_t x, uint32_t y)
{
    uint32_t raddr;
    uint64_t pv;
    asm("mov.b64 %0, {%1, %2};" : "=l"(pv) : "r"(x), "r"(y));
    asm volatile("mapa.shared::cluster.u32 %0, %1, %2;" : "=r"(raddr) : "r"(laddr), "r"(rank));
    asm volatile("st.shared::cluster.u64 [%0], %1;" :: "r"(raddr), "l"(pv) : "memory");
}

// ============================================================================
// tf32 warp-mma GEMM (validated): C[128,128] tiles, 8 warps 2x4, m16n8k8
// ============================================================================
#define GK 32

__global__ __launch_bounds__(256, 2)
void k_xproj_mma(const float* __restrict__ X, const float* __restrict__ Wih,
                 const float* __restrict__ bias)
{
    __shared__ uint32_t As[128][36];
    __shared__ uint32_t Ws[128][36];

    const int tid = threadIdx.x, lane = tid & 31, wid = tid >> 5;
    const int warpM = wid >> 2, warpN = wid & 3;
    const int b = blockIdx.y, n0 = blockIdx.x * 128;
    const int g = lane >> 2, q = lane & 3;

    float acc[4][4][4];
#pragma unroll
    for (int i = 0; i < 4; i++)
#pragma unroll
        for (int j = 0; j < 4; j++)
#pragma unroll
            for (int r = 0; r < 4; r++) acc[i][j][r] = 0.f;

    for (int c = 0; c < INF / GK; c++) {
        const int k0 = c * GK;
#pragma unroll
        for (int l = 0; l < 4; l++) {
            int f = tid + l * 256;
            int row = f >> 3, c4 = f & 7;
            float4 v = *(const float4*)(X + ((size_t)b * NA + row) * INF + k0 + c4 * 4);
            *(uint4*)&As[row][c4 * 4] =
                make_uint4(f2tf32(v.x), f2tf32(v.y), f2tf32(v.z), f2tf32(v.w));
            float4 w = *(const float4*)(Wih + (size_t)(n0 + row) * INF + k0 + c4 * 4);
            *(uint4*)&Ws[row][c4 * 4] =
                make_uint4(f2tf32(w.x), f2tf32(w.y), f2tf32(w.z), f2tf32(w.w));
        }
        __syncthreads();
#pragma unroll
        for (int kk = 0; kk < GK; kk += 8) {
            uint32_t bf[4][2];
#pragma unroll
            for (int nt = 0; nt < 4; nt++) {
                int nb = warpN * 32 + nt * 8 + g;
                bf[nt][0] = Ws[nb][kk + q];
                bf[nt][1] = Ws[nb][kk + q + 4];
            }
#pragma unroll
            for (int mt = 0; mt < 4; mt++) {
                int mb = warpM * 64 + mt * 16 + g;
                uint32_t a0 = As[mb][kk + q];
                uint32_t a1 = As[mb + 8][kk + q];
                uint32_t a2 = As[mb][kk + q + 4];
                uint32_t a3 = As[mb + 8][kk + q + 4];
#pragma unroll
                for (int nt = 0; nt < 4; nt++)
                    mma_tf32_16n8k8(acc[mt][nt], a0, a1, a2, a3, bf[nt][0], bf[nt][1]);
            }
        }
        __syncthreads();
    }

#pragma unroll
    for (int mt = 0; mt < 4; mt++) {
#pragma unroll
        for (int nt = 0; nt < 4; nt++) {
            int mrow = warpM * 64 + mt * 16 + g;
            int ncol = n0 + warpN * 32 + nt * 8 + 2 * q;
            float b0 = __ldg(bias + ncol), b1 = __ldg(bias + ncol + 1);
            float* o = g_xproj + ((size_t)b * NA + mrow) * G3 + ncol;
            *(float2*)o = make_float2(acc[mt][nt][0] + b0, acc[mt][nt][1] + b1);
            float* o2 = o + 8 * G3;
            *(float2*)o2 = make_float2(acc[mt][nt][2] + b0, acc[mt][nt][3] + b1);
        }
    }
}

__global__ __launch_bounds__(256, 2)
void k_fc_mma(const int* __restrict__ bonded, const float* __restrict__ Wfc,
              const float* __restrict__ bfc, float* __restrict__ Out)
{
    __shared__ uint32_t As[128][36];
    __shared__ uint32_t Ws[128][36];
    __shared__ int idx_s[NA * VV];

    const int tid = threadIdx.x, lane = tid & 31, wid = tid >> 5;
    const int warpM = wid >> 2, warpN = wid & 3;
    const int b = blockIdx.y, n0 = blockIdx.x * 128;
    const int g = lane >> 2, q = lane & 3;

    for (int i = tid; i < NA * VV; i += 256)
        idx_s[i] = bonded[(size_t)b * NA * VV + i];

    float acc[4][4][4];
#pragma unroll
    for (int i = 0; i < 4; i++)
#pragma unroll
        for (int j = 0; j < 4; j++)
#pragma unroll
            for (int r = 0; r < 4; r++) acc[i][j][r] = 0.f;

    const float* rnn_b = g_rnn + (size_t)b * NA * HH;
    __syncthreads();

    for (int c = 0; c < KFC / GK; c++) {
        const int v = c >> 3, hsub = (c << 5) & 255, k0 = c * GK;
#pragma unroll
        for (int l = 0; l < 4; l++) {
            int f = tid + l * 256;
            int row = f >> 3, c4 = f & 7;
            float4 val = *(const float4*)(rnn_b + (size_t)idx_s[row * VV + v] * HH + hsub + c4 * 4);
            *(uint4*)&As[row][c4 * 4] =
                make_uint4(f2tf32(val.x), f2tf32(val.y), f2tf32(val.z), f2tf32(val.w));
            float4 w = *(const float4*)(Wfc + (size_t)(n0 + row) * KFC + k0 + c4 * 4);
            *(uint4*)&Ws[row][c4 * 4] =
                make_uint4(f2tf32(w.x), f2tf32(w.y), f2tf32(w.z), f2tf32(w.w));
        }
        __syncthreads();
#pragma unroll
        for (int kk = 0; kk < GK; kk += 8) {
            uint32_t bf[4][2];
#pragma unroll
            for (int nt = 0; nt < 4; nt++) {
                int nb = warpN * 32 + nt * 8 + g;
                bf[nt][0] = Ws[nb][kk + q];
                bf[nt][1] = Ws[nb][kk + q + 4];
            }
#pragma unroll
            for (int mt = 0; mt < 4; mt++) {
                int mb = warpM * 64 + mt * 16 + g;
                uint32_t a0 = As[mb][kk + q];
                uint32_t a1 = As[mb + 8][kk + q];
                uint32_t a2 = As[mb][kk + q + 4];
                uint32_t a3 = As[mb + 8][kk + q + 4];
#pragma unroll
                for (int nt = 0; nt < 4; nt++)
                    mma_tf32_16n8k8(acc[mt][nt], a0, a1, a2, a3, bf[nt][0], bf[nt][1]);
            }
        }
        __syncthreads();
    }

#pragma unroll
    for (int mt = 0; mt < 4; mt++) {
#pragma unroll
        for (int nt = 0; nt < 4; nt++) {
            int mrow = warpM * 64 + mt * 16 + g;
            int ncol = n0 + warpN * 32 + nt * 8 + 2 * q;
            float b0 = __ldg(bfc + ncol), b1 = __ldg(bfc + ncol + 1);
            float y0 = acc[mt][nt][0] + b0, y1 = acc[mt][nt][1] + b1;
            float y2 = acc[mt][nt][2] + b0, y3 = acc[mt][nt][3] + b1;
            y0 = y0 >= 0.f ? y0 : 0.1f * y0;
            y1 = y1 >= 0.f ? y1 : 0.1f * y1;
            y2 = y2 >= 0.f ? y2 : 0.1f * y2;
            y3 = y3 >= 0.f ? y3 : 0.1f * y3;
            float* o = Out + ((size_t)b * NA + mrow) * OUTF + ncol;
            *(float2*)o = make_float2(y0, y1);
            *(float2*)(o + 8 * OUTF) = make_float2(y2, y3);
        }
    }
}

// ============================================================================
// GRU v3b: 16 clusters x 8 CTAs x 256 thr (8 warps = 2/SMSP).
// Warp w: j-octet wj=w&3, k-half kh=w>>2. h exchanged as tf32; h_prev in regs.
// Partial exchange: each thread scalar-stores ONLY the 6 floats its partner
// (w^4) needs, stride 7 words (odd -> conflict-free, 4B-aligned scalar STS).
// ============================================================================
#define GWS      260
#define GW_WORDS (96 * GWS)                 // 24960
#define GH_BUF   (16 * GWS)                 // 4160 (u32 tf32 words)
#define RED_OFF  (GW_WORDS + 2 * GH_BUF)    // 33280
#define RED_WORDS (256 * 7)                 // 1792
#define GRU_SMEM ((RED_OFF + RED_WORDS) * 4)   // 140288 B

__global__ void __cluster_dims__(8, 1, 1) __launch_bounds__(256, 1)
k_gru_mma(const float* __restrict__ W_hh, const float* __restrict__ b_hh)
{
    extern __shared__ uint32_t smg[];
    uint32_t* Wsm = smg;                    // tf32 W slice
    uint32_t* hs  = smg + GW_WORDS;         // 2 x GH_BUF tf32 h
    float*    red = (float*)(smg + RED_OFF);

    const int tid = threadIdx.x, lane = tid & 31, w = tid >> 5;
    const int wj = w & 3, kh = w >> 2;
    const int g = lane >> 2, q = lane & 3;
    uint32_t rank;
    asm("mov.u32 %0, %%cluster_ctarank;" : "=r"(rank));
    const int b0   = (blockIdx.x >> 3) * 16;
    const int jb   = wj * 8 + 2 * q;
    const int jg0  = (int)rank * 32 + jb;          // global j pair base
    const int myb  = b0 + g + kh * 8;              // batch this warp finalizes
    const int myrow = g + kh * 8;                  // h row this warp pushes

    // ---- W slice -> tf32 SMEM ----
    for (int i = tid; i < 96 * 64; i += 256) {
        int r = i >> 6, k4 = i & 63;
        int gate = r >> 5, jl = r & 31;
        float4 v = *(const float4*)(W_hh +
            ((size_t)(gate * 256 + (int)rank * 32 + jl)) * 256 + k4 * 4);
        uint32_t* d = Wsm + (size_t)r * GWS + k4 * 4;
        d[0] = f2tf32(v.x); d[1] = f2tf32(v.y);
        d[2] = f2tf32(v.z); d[3] = f2tf32(v.w);
    }
    for (int i = tid; i < GH_BUF; i += 256) hs[i] = 0u;   // t=0 state buffer
    __syncthreads();

    const float2 brv = *(const float2*)(b_hh + jg0);
    const float2 bzv = *(const float2*)(b_hh + 256 + jg0);
    const float2 bnv = *(const float2*)(b_hh + 512 + jg0);
    const uint32_t hs_addr = smem_u32(hs);
    const uint32_t* WR = Wsm + (size_t)(0  + wj * 8 + g) * GWS + kh * 128;
    const uint32_t* WZ = Wsm + (size_t)(32 + wj * 8 + g) * GWS + kh * 128;
    const uint32_t* WN = Wsm + (size_t)(64 + wj * 8 + g) * GWS + kh * 128;
    float* myred = red + (size_t)(w * 32 + lane) * 7;      // I write partner's 6
    const float* pred_ = red + (size_t)((w ^ 4) * 32 + lane) * 7;
    const int ib = kh * 2;                  // my accumulator pair index
    const int ob = 2 - ib;                  // the pair my partner needs

    float hp0 = 0.f, hp1 = 0.f;             // h_prev for (myb, j0/j1) in regs

    for (int t = 0; t < NA; t++) {
        const uint32_t* hc = hs + (t & 1) * GH_BUF;
        const uint32_t hn_base = hs_addr + (uint32_t)(((t + 1) & 1) * GH_BUF) * 4u;

        // prefetch xproj for my batch only
        const float* xp = g_xproj + ((size_t)myb * NA + t) * G3 + jg0;
        float2 xr = __ldg((const float2*)xp);
        float2 xz = __ldg((const float2*)(xp + 256));
        float2 xn = __ldg((const float2*)(xp + 512));

        float aR[4] = {0.f, 0.f, 0.f, 0.f};
        float aZ[4] = {0.f, 0.f, 0.f, 0.f};
        float aN[4] = {0.f, 0.f, 0.f, 0.f};

        const uint32_t* hA = hc + g * GWS + kh * 128;
        const uint32_t* hB = hc + (g + 8) * GWS + kh * 128;
#pragma unroll
        for (int kk = 0; kk < 128; kk += 8) {
            uint32_t a0 = hA[kk + q];
            uint32_t a1 = hB[kk + q];
            uint32_t a2 = hA[kk + q + 4];
            uint32_t a3 = hB[kk + q + 4];
            mma_tf32_16n8k8(aR, a0, a1, a2, a3, WR[kk + q], WR[kk + q + 4]);
            mma_tf32_16n8k8(aZ, a0, a1, a2, a3, WZ[kk + q], WZ[kk + q + 4]);
            mma_tf32_16n8k8(aN, a0, a1, a2, a3, WN[kk + q], WN[kk + q + 4]);
        }

        // exchange: scalar-store the 6 floats partner (w^4) consumes
        myred[0] = aR[ob]; myred[1] = aR[ob + 1];
        myred[2] = aZ[ob]; myred[3] = aZ[ob + 1];
        myred[4] = aN[ob]; myred[5] = aN[ob + 1];
        __syncthreads();
        float sR0 = aR[ib]     + pred_[0];
        float sR1 = aR[ib + 1] + pred_[1];
        float sZ0 = aZ[ib]     + pred_[2];
        float sZ1 = aZ[ib + 1] + pred_[3];
        float sN0 = aN[ib]     + pred_[4];
        float sN1 = aN[ib + 1] + pred_[5];

        // gates for (myb, j0), (myb, j1)
        float r0 = 1.f / (1.f + __expf(-(xr.x + sR0 + brv.x)));
        float r1 = 1.f / (1.f + __expf(-(xr.y + sR1 + brv.y)));
        float z0 = 1.f / (1.f + __expf(-(xz.x + sZ0 + bzv.x)));
        float z1 = 1.f / (1.f + __expf(-(xz.y + sZ1 + bzv.y)));
        float n0 = tanhf(xn.x + r0 * (sN0 + bnv.x));
        float n1 = tanhf(xn.y + r1 * (sN1 + bnv.y));
        float h0 = (1.f - z0) * n0 + z0 * hp0;
        float h1 = (1.f - z1) * n1 + z1 * hp1;
        hp0 = h0; hp1 = h1;

        // push tf32 pair (8B, aligned: jg0 even) to all 8 cluster CTAs
        uint32_t t0 = f2tf32(h0), t1 = f2tf32(h1);
        uint32_t laddr = hn_base + (uint32_t)(myrow * GWS + jg0) * 4u;
#pragma unroll
        for (uint32_t c = 0; c < 8; c++)
            st_cluster_u32pair(laddr, c, t0, t1);

        asm volatile("barrier.cluster.arrive.aligned;" ::: "memory");
        *(float2*)(g_rnn + ((size_t)myb * NA + t) * HH + jg0) = make_float2(h0, h1);
        asm volatile("barrier.cluster.wait.aligned;" ::: "memory");
    }
}

// ---------------- launch ------------------------------------------------------
extern "C" void kernel_launch(void* const* d_in, const int* in_sizes, int n_in,
                              void* d_out, int out_size)
{
    const float* x      = (const float*)d_in[0];
    const int*   bonded = (const int*)  d_in[1];
    const float* W_ih   = (const float*)d_in[2];
    const float* W_hh   = (const float*)d_in[3];
    const float* b_ih   = (const float*)d_in[4];
    const float* b_hh   = (const float*)d_in[5];
    const float* W_fc   = (const float*)d_in[6];
    const float* b_fc   = (const float*)d_in[7];
    float* out = (float*)d_out;

    cudaFuncSetAttribute(k_gru_mma,
                         cudaFuncAttributeMaxDynamicSharedMemorySize, GRU_SMEM);

    // two dummies: keeps the profiled slot on k_gru_mma
    k_dummy<<<1, 32>>>();
    k_dummy<<<1, 32>>>();

    // 1) x_proj (tf32 mma)
    k_xproj_mma<<<dim3(G3 / 128, BB), 256>>>(x, W_ih, b_ih);

    // 2) GRU on tensor cores (tf32 mma, fp32 state in regs)
    k_gru_mma<<<128, 256, GRU_SMEM>>>(W_hh, b_hh);

    // 3) FC (tf32 mma, gather fused)
    k_fc_mma<<<dim3(OUTF / 128, BB), 256>>>(bonded, W_fc, b_fc, out);
}

// round 11
// speedup vs baseline: 2.0522x; 1.0171x over previous
#include <cuda_runtime.h>
#include <math.h>
#include <stdint.h>

// Problem dims
#define BB    256
#define NA    128
#define INF   128
#define HH    256
#define G3    768
#define VV    6
#define OUTF  256
#define KFC   1536

// ---------------- scratch ----------------------------------------------------
__device__ float g_xproj[(size_t)BB * NA * G3];
__device__ float g_rnn  [(size_t)BB * NA * HH];

__global__ void k_dummy() {}

// ---------------- helpers ----------------------------------------------------
__device__ __forceinline__ uint32_t smem_u32(const void* p)
{
    uint32_t a;
    asm("{ .reg .u64 t; cvta.to.shared.u64 t, %1; cvt.u32.u64 %0, t; }" : "=r"(a) : "l"(p));
    return a;
}

__device__ __forceinline__ uint32_t f2tf32(float v)
{
    uint32_t u;
    asm("cvt.rna.tf32.f32 %0, %1;" : "=r"(u) : "f"(v));
    return u;
}

__device__ __forceinline__ void mma_tf32_16n8k8(float* c, uint32_t a0, uint32_t a1,
                                                uint32_t a2, uint32_t a3,
                                                uint32_t b0, uint32_t b1)
{
    asm volatile(
        "mma.sync.aligned.m16n8k8.row.col.f32.tf32.tf32.f32 "
        "{%0,%1,%2,%3}, {%4,%5,%6,%7}, {%8,%9}, {%0,%1,%2,%3};"
        : "+f"(c[0]), "+f"(c[1]), "+f"(c[2]), "+f"(c[3])
        : "r"(a0), "r"(a1), "r"(a2), "r"(a3), "r"(b0), "r"(b1));
}

// async DSMEM store pair with tx credit to remote mbarrier
__device__ __forceinline__ void st_async_pair(uint32_t laddr, uint32_t lmbar,
                                              uint32_t rank, uint32_t x, uint32_t y)
{
    uint32_t ra, rm;
    uint64_t pv;
    asm("mov.b64 %0, {%1, %2};" : "=l"(pv) : "r"(x), "r"(y));
    asm volatile("mapa.shared::cluster.u32 %0, %1, %2;" : "=r"(ra) : "r"(laddr), "r"(rank));
    asm volatile("mapa.shared::cluster.u32 %0, %1, %2;" : "=r"(rm) : "r"(lmbar), "r"(rank));
    asm volatile("st.async.shared::cluster.mbarrier::complete_tx::bytes.u64 [%0], %1, [%2];"
                 :: "r"(ra), "l"(pv), "r"(rm) : "memory");
}

#define MBAR_INIT(addr, cnt) \
    asm volatile("mbarrier.init.shared.b64 [%0], %1;" :: "r"(addr), "r"(cnt) : "memory")

#define MBAR_EXPECT_TX(addr, n) \
    asm volatile("mbarrier.arrive.expect_tx.shared.b64 _, [%0], %1;" :: "r"(addr), "r"(n) : "memory")

#define MBAR_WAIT_CL(addr, par) do {                                           \
    uint32_t _m = (addr), _p = (par), _d;                                      \
    asm volatile("{\n\t.reg .pred p;\n\t"                                      \
        "mbarrier.try_wait.parity.acquire.cluster.shared::cta.b64 p, [%1], %2;\n\t" \
        "selp.b32 %0, 1, 0, p;\n\t}" : "=r"(_d) : "r"(_m), "r"(_p) : "memory");\
    if (!_d) {                                                                 \
        asm volatile("{\n\t.reg .pred P1;\n\tWL_%=:\n\t"                       \
            "mbarrier.try_wait.parity.acquire.cluster.shared::cta.b64 P1, [%0], %1, 0x989680;\n\t" \
            "@P1 bra.uni WD_%=;\n\tbra.uni WL_%=;\n\tWD_%=:\n\t}"              \
            :: "r"(_m), "r"(_p) : "memory");                                   \
    }                                                                          \
} while (0)

// ============================================================================
// tf32 warp-mma GEMM (validated): C[128,128] tiles, 8 warps 2x4, m16n8k8
// ============================================================================
#define GK 32

__global__ __launch_bounds__(256, 2)
void k_xproj_mma(const float* __restrict__ X, const float* __restrict__ Wih,
                 const float* __restrict__ bias)
{
    __shared__ uint32_t As[128][36];
    __shared__ uint32_t Ws[128][36];

    const int tid = threadIdx.x, lane = tid & 31, wid = tid >> 5;
    const int warpM = wid >> 2, warpN = wid & 3;
    const int b = blockIdx.y, n0 = blockIdx.x * 128;
    const int g = lane >> 2, q = lane & 3;

    float acc[4][4][4];
#pragma unroll
    for (int i = 0; i < 4; i++)
#pragma unroll
        for (int j = 0; j < 4; j++)
#pragma unroll
            for (int r = 0; r < 4; r++) acc[i][j][r] = 0.f;

    for (int c = 0; c < INF / GK; c++) {
        const int k0 = c * GK;
#pragma unroll
        for (int l = 0; l < 4; l++) {
            int f = tid + l * 256;
            int row = f >> 3, c4 = f & 7;
            float4 v = *(const float4*)(X + ((size_t)b * NA + row) * INF + k0 + c4 * 4);
            *(uint4*)&As[row][c4 * 4] =
                make_uint4(f2tf32(v.x), f2tf32(v.y), f2tf32(v.z), f2tf32(v.w));
            float4 w = *(const float4*)(Wih + (size_t)(n0 + row) * INF + k0 + c4 * 4);
            *(uint4*)&Ws[row][c4 * 4] =
                make_uint4(f2tf32(w.x), f2tf32(w.y), f2tf32(w.z), f2tf32(w.w));
        }
        __syncthreads();
#pragma unroll
        for (int kk = 0; kk < GK; kk += 8) {
            uint32_t bf[4][2];
#pragma unroll
            for (int nt = 0; nt < 4; nt++) {
                int nb = warpN * 32 + nt * 8 + g;
                bf[nt][0] = Ws[nb][kk + q];
                bf[nt][1] = Ws[nb][kk + q + 4];
            }
#pragma unroll
            for (int mt = 0; mt < 4; mt++) {
                int mb = warpM * 64 + mt * 16 + g;
                uint32_t a0 = As[mb][kk + q];
                uint32_t a1 = As[mb + 8][kk + q];
                uint32_t a2 = As[mb][kk + q + 4];
                uint32_t a3 = As[mb + 8][kk + q + 4];
#pragma unroll
                for (int nt = 0; nt < 4; nt++)
                    mma_tf32_16n8k8(acc[mt][nt], a0, a1, a2, a3, bf[nt][0], bf[nt][1]);
            }
        }
        __syncthreads();
    }

#pragma unroll
    for (int mt = 0; mt < 4; mt++) {
#pragma unroll
        for (int nt = 0; nt < 4; nt++) {
            int mrow = warpM * 64 + mt * 16 + g;
            int ncol = n0 + warpN * 32 + nt * 8 + 2 * q;
            float b0 = __ldg(bias + ncol), b1 = __ldg(bias + ncol + 1);
            float* o = g_xproj + ((size_t)b * NA + mrow) * G3 + ncol;
            *(float2*)o = make_float2(acc[mt][nt][0] + b0, acc[mt][nt][1] + b1);
            float* o2 = o + 8 * G3;
            *(float2*)o2 = make_float2(acc[mt][nt][2] + b0, acc[mt][nt][3] + b1);
        }
    }
}

__global__ __launch_bounds__(256, 2)
void k_fc_mma(const int* __restrict__ bonded, const float* __restrict__ Wfc,
              const float* __restrict__ bfc, float* __restrict__ Out)
{
    __shared__ uint32_t As[128][36];
    __shared__ uint32_t Ws[128][36];
    __shared__ int idx_s[NA * VV];

    const int tid = threadIdx.x, lane = tid & 31, wid = tid >> 5;
    const int warpM = wid >> 2, warpN = wid & 3;
    const int b = blockIdx.y, n0 = blockIdx.x * 128;
    const int g = lane >> 2, q = lane & 3;

    for (int i = tid; i < NA * VV; i += 256)
        idx_s[i] = bonded[(size_t)b * NA * VV + i];

    float acc[4][4][4];
#pragma unroll
    for (int i = 0; i < 4; i++)
#pragma unroll
        for (int j = 0; j < 4; j++)
#pragma unroll
            for (int r = 0; r < 4; r++) acc[i][j][r] = 0.f;

    const float* rnn_b = g_rnn + (size_t)b * NA * HH;
    __syncthreads();

    for (int c = 0; c < KFC / GK; c++) {
        const int v = c >> 3, hsub = (c << 5) & 255, k0 = c * GK;
#pragma unroll
        for (int l = 0; l < 4; l++) {
            int f = tid + l * 256;
            int row = f >> 3, c4 = f & 7;
            float4 val = *(const float4*)(rnn_b + (size_t)idx_s[row * VV + v] * HH + hsub + c4 * 4);
            *(uint4*)&As[row][c4 * 4] =
                make_uint4(f2tf32(val.x), f2tf32(val.y), f2tf32(val.z), f2tf32(val.w));
            float4 w = *(const float4*)(Wfc + (size_t)(n0 + row) * KFC + k0 + c4 * 4);
            *(uint4*)&Ws[row][c4 * 4] =
                make_uint4(f2tf32(w.x), f2tf32(w.y), f2tf32(w.z), f2tf32(w.w));
        }
        __syncthreads();
#pragma unroll
        for (int kk = 0; kk < GK; kk += 8) {
            uint32_t bf[4][2];
#pragma unroll
            for (int nt = 0; nt < 4; nt++) {
                int nb = warpN * 32 + nt * 8 + g;
                bf[nt][0] = Ws[nb][kk + q];
                bf[nt][1] = Ws[nb][kk + q + 4];
            }
#pragma unroll
            for (int mt = 0; mt < 4; mt++) {
                int mb = warpM * 64 + mt * 16 + g;
                uint32_t a0 = As[mb][kk + q];
                uint32_t a1 = As[mb + 8][kk + q];
                uint32_t a2 = As[mb][kk + q + 4];
                uint32_t a3 = As[mb + 8][kk + q + 4];
#pragma unroll
                for (int nt = 0; nt < 4; nt++)
                    mma_tf32_16n8k8(acc[mt][nt], a0, a1, a2, a3, bf[nt][0], bf[nt][1]);
            }
        }
        __syncthreads();
    }

#pragma unroll
    for (int mt = 0; mt < 4; mt++) {
#pragma unroll
        for (int nt = 0; nt < 4; nt++) {
            int mrow = warpM * 64 + mt * 16 + g;
            int ncol = n0 + warpN * 32 + nt * 8 + 2 * q;
            float b0 = __ldg(bfc + ncol), b1 = __ldg(bfc + ncol + 1);
            float y0 = acc[mt][nt][0] + b0, y1 = acc[mt][nt][1] + b1;
            float y2 = acc[mt][nt][2] + b0, y3 = acc[mt][nt][3] + b1;
            y0 = y0 >= 0.f ? y0 : 0.1f * y0;
            y1 = y1 >= 0.f ? y1 : 0.1f * y1;
            y2 = y2 >= 0.f ? y2 : 0.1f * y2;
            y3 = y3 >= 0.f ? y3 : 0.1f * y3;
            float* o = Out + ((size_t)b * NA + mrow) * OUTF + ncol;
            *(float2*)o = make_float2(y0, y1);
            *(float2*)(o + 8 * OUTF) = make_float2(y2, y3);
        }
    }
}

// ============================================================================
// GRU v4: async-paced exchange. 16 clusters x 8 CTAs x 256 thr.
// st.async + per-buffer mbarrier (tx=16384B) replaces cluster rendezvous:
// each CTA proceeds when ITS inbox for the step is complete. Double-buffered
// h and red; expect_tx re-armed post-wait; one cluster.sync at init only.
// ============================================================================
#define GWS      260
#define GW_WORDS (96 * GWS)                 // 24960
#define GH_BUF   (16 * GWS)                 // 4160 (u32 tf32 words)
#define RED_OFF  (GW_WORDS + 2 * GH_BUF)    // 33280
#define RED_WORDS (256 * 7)                 // 1792 per parity buffer
#define MB_OFF   (RED_OFF + 2 * RED_WORDS)  // 36864 words (8B-aligned *4)
#define GRU_SMEM ((MB_OFF + 4) * 4)         // 147472 B
#define TX_BYTES 16384u

__global__ void __cluster_dims__(8, 1, 1) __launch_bounds__(256, 1)
k_gru_mma(const float* __restrict__ W_hh, const float* __restrict__ b_hh)
{
    extern __shared__ uint32_t smg[];
    uint32_t* Wsm = smg;                    // tf32 W slice
    uint32_t* hs  = smg + GW_WORDS;         // 2 x GH_BUF tf32 h
    float*    red = (float*)(smg + RED_OFF);

    const int tid = threadIdx.x, lane = tid & 31, w = tid >> 5;
    const int wj = w & 3, kh = w >> 2;
    const int g = lane >> 2, q = lane & 3;
    uint32_t rank;
    asm("mov.u32 %0, %%cluster_ctarank;" : "=r"(rank));
    const int b0   = (blockIdx.x >> 3) * 16;
    const int jb   = wj * 8 + 2 * q;
    const int jg0  = (int)rank * 32 + jb;          // global j pair base
    const int myb  = b0 + g + kh * 8;              // batch this warp finalizes
    const int myrow = g + kh * 8;                  // h row this warp pushes

    const uint32_t sbase   = smem_u32(smg);
    const uint32_t hs_addr = sbase + GW_WORDS * 4u;
    const uint32_t mb_base = sbase + MB_OFF * 4u;  // mb0 @ +0, mb1 @ +8

    // ---- W slice -> tf32 SMEM ----
    for (int i = tid; i < 96 * 64; i += 256) {
        int r = i >> 6, k4 = i & 63;
        int gate = r >> 5, jl = r & 31;
        float4 v = *(const float4*)(W_hh +
            ((size_t)(gate * 256 + (int)rank * 32 + jl)) * 256 + k4 * 4);
        uint32_t* d = Wsm + (size_t)r * GWS + k4 * 4;
        d[0] = f2tf32(v.x); d[1] = f2tf32(v.y);
        d[2] = f2tf32(v.z); d[3] = f2tf32(v.w);
    }
    for (int i = tid; i < GH_BUF; i += 256) hs[i] = 0u;   // t=0 state buffer
    if (tid == 0) {
        MBAR_INIT(mb_base + 0u, 1);
        MBAR_INIT(mb_base + 8u, 1);
        MBAR_EXPECT_TX(mb_base + 0u, TX_BYTES);
        MBAR_EXPECT_TX(mb_base + 8u, TX_BYTES);
    }
    __syncthreads();
    // all CTAs' mbarriers must be armed before any st.async targets them
    asm volatile("barrier.cluster.arrive.aligned;" ::: "memory");
    asm volatile("barrier.cluster.wait.aligned;" ::: "memory");

    const float2 brv = *(const float2*)(b_hh + jg0);
    const float2 bzv = *(const float2*)(b_hh + 256 + jg0);
    const float2 bnv = *(const float2*)(b_hh + 512 + jg0);
    const uint32_t* WR = Wsm + (size_t)(0  + wj * 8 + g) * GWS + kh * 128;
    const uint32_t* WZ = Wsm + (size_t)(32 + wj * 8 + g) * GWS + kh * 128;
    const uint32_t* WN = Wsm + (size_t)(64 + wj * 8 + g) * GWS + kh * 128;
    const int ib = kh * 2;                  // my accumulator pair index
    const int ob = 2 - ib;                  // the pair my partner (w^4) needs

    float hp0 = 0.f, hp1 = 0.f;             // h_prev for (myb, j0/j1) in regs

    for (int t = 0; t < NA; t++) {
        const int buf = t & 1;
        const uint32_t* hc = hs + buf * GH_BUF;
        const uint32_t cur_mb = mb_base + (uint32_t)buf * 8u;

        if (t >= 1) {
            MBAR_WAIT_CL(cur_mb, ((t - 1) >> 1) & 1);
            if (tid == 0) MBAR_EXPECT_TX(cur_mb, TX_BYTES);   // re-arm for t+2
        }

        // prefetch xproj for my batch only
        const float* xp = g_xproj + ((size_t)myb * NA + t) * G3 + jg0;
        float2 xr = __ldg((const float2*)xp);
        float2 xz = __ldg((const float2*)(xp + 256));
        float2 xn = __ldg((const float2*)(xp + 512));

        float aR[4] = {0.f, 0.f, 0.f, 0.f};
        float aZ[4] = {0.f, 0.f, 0.f, 0.f};
        float aN[4] = {0.f, 0.f, 0.f, 0.f};

        const uint32_t* hA = hc + g * GWS + kh * 128;
        const uint32_t* hB = hc + (g + 8) * GWS + kh * 128;
#pragma unroll
        for (int kk = 0; kk < 128; kk += 8) {
            uint32_t a0 = hA[kk + q];
            uint32_t a1 = hB[kk + q];
            uint32_t a2 = hA[kk + q + 4];
            uint32_t a3 = hB[kk + q + 4];
            mma_tf32_16n8k8(aR, a0, a1, a2, a3, WR[kk + q], WR[kk + q + 4]);
            mma_tf32_16n8k8(aZ, a0, a1, a2, a3, WZ[kk + q], WZ[kk + q + 4]);
            mma_tf32_16n8k8(aN, a0, a1, a2, a3, WN[kk + q], WN[kk + q + 4]);
        }

        // exchange partials with partner warp (w^4); red double-buffered by parity
        float* myred = red + buf * RED_WORDS + (size_t)(w * 32 + lane) * 7;
        const float* pred_ = red + buf * RED_WORDS + (size_t)((w ^ 4) * 32 + lane) * 7;
        myred[0] = aR[ob]; myred[1] = aR[ob + 1];
        myred[2] = aZ[ob]; myred[3] = aZ[ob + 1];
        myred[4] = aN[ob]; myred[5] = aN[ob + 1];
        __syncthreads();
        float sR0 = aR[ib]     + pred_[0];
        float sR1 = aR[ib + 1] + pred_[1];
        float sZ0 = aZ[ib]     + pred_[2];
        float sZ1 = aZ[ib + 1] + pred_[3];
        float sN0 = aN[ib]     + pred_[4];
        float sN1 = aN[ib + 1] + pred_[5];

        // gates for (myb, j0), (myb, j1)
        float r0 = 1.f / (1.f + __expf(-(xr.x + sR0 + brv.x)));
        float r1 = 1.f / (1.f + __expf(-(xr.y + sR1 + brv.y)));
        float z0 = 1.f / (1.f + __expf(-(xz.x + sZ0 + bzv.x)));
        float z1 = 1.f / (1.f + __expf(-(xz.y + sZ1 + bzv.y)));
        float n0 = tanhf(xn.x + r0 * (sN0 + bnv.x));
        float n1 = tanhf(xn.y + r1 * (sN1 + bnv.y));
        float h0 = (1.f - z0) * n0 + z0 * hp0;
        float h1 = (1.f - z1) * n1 + z1 * hp1;
        hp0 = h0; hp1 = h1;

        // async push tf32 pair to all 8 cluster CTAs (skip useless last push)
        if (t < NA - 1) {
            const int nbuf = (t + 1) & 1;
            uint32_t t0 = f2tf32(h0), t1 = f2tf32(h1);
            uint32_t laddr = hs_addr + (uint32_t)(nbuf * GH_BUF + myrow * GWS + jg0) * 4u;
            uint32_t lmbar = mb_base + (uint32_t)nbuf * 8u;
#pragma unroll
            for (uint32_t c = 0; c < 8; c++)
                st_async_pair(laddr, lmbar, c, t0, t1);
        }

        *(float2*)(g_rnn + ((size_t)myb * NA + t) * HH + jg0) = make_float2(h0, h1);
    }
}

// ---------------- launch ------------------------------------------------------
extern "C" void kernel_launch(void* const* d_in, const int* in_sizes, int n_in,
                              void* d_out, int out_size)
{
    const float* x      = (const float*)d_in[0];
    const int*   bonded = (const int*)  d_in[1];
    const float* W_ih   = (const float*)d_in[2];
    const float* W_hh   = (const float*)d_in[3];
    const float* b_ih   = (const float*)d_in[4];
    const float* b_hh   = (const float*)d_in[5];
    const float* W_fc   = (const float*)d_in[6];
    const float* b_fc   = (const float*)d_in[7];
    float* out = (float*)d_out;

    cudaFuncSetAttribute(k_gru_mma,
                         cudaFuncAttributeMaxDynamicSharedMemorySize, GRU_SMEM);

    // two dummies: keeps the profiled slot on k_gru_mma
    k_dummy<<<1, 32>>>();
    k_dummy<<<1, 32>>>();

    // 1) x_proj (tf32 mma)
    k_xproj_mma<<<dim3(G3 / 128, BB), 256>>>(x, W_ih, b_ih);

    // 2) GRU on tensor cores, async mbarrier-paced cluster exchange
    k_gru_mma<<<128, 256, GRU_SMEM>>>(W_hh, b_hh);

    // 3) FC (tf32 mma, gather fused)
    k_fc_mma<<<dim3(OUTF / 128, BB), 256>>>(bonded, W_fc, b_fc, out);
}